// round 11
// baseline (speedup 1.0000x reference)
#include <cuda_runtime.h>
#include <cuda_fp16.h>
#include <math.h>
#include <stdint.h>

#define TT 4
#define NN 20000
#define EE 320000
#define RR 2
#define DD 64
#define HH 4
#define CC 64
#define HC 256   // H*C
#define ZZ 8     // T*R

typedef unsigned long long ull;

// 16B edge record: fp16 weights (8B) + src + pad -> ONE LDG.128 per edge in gather
struct __align__(16) ERec16 {
    unsigned int w01;  // half2: heads 0,1
    unsigned int w23;  // half2: heads 2,3
    int src;
    int pad;
};

// ----------------- scratch (static device globals; no allocation) -----------------
__device__ __align__(16) float g_agg[ZZ * NN * HC];
__device__ __align__(16) float g_als[ZZ * NN * HH];
__device__ __align__(16) float g_ald[ZZ * NN * HH];
__device__ __align__(16) float g_intra[TT * NN * RR * CC];
__device__ float g_ssum[TT * RR];
__device__ float g_beta[TT * RR];
__device__ __align__(16) float g_xg[TT * NN * HC];
__device__ __align__(16) float g_lh[NN * CC];
__device__ __align__(16) float g_lc[NN * CC];
__device__ __align__(16) float g_feats[NN * TT * CC];
__device__ float g_WihT[DD * HC];
__device__ float g_WhhT[DD * HC];
__device__ float g_biassum[HC];
__device__ __align__(16) float g_folds[RR * DD * HH];
__device__ __align__(16) float g_foldd[RR * DD * HH];
__device__ float g_Bstack[RR * HC * CC];
__device__ int g_cnt[ZZ * NN];
__device__ int g_off[ZZ * (NN + 1)];
__device__ int g_pos[ZZ * NN];
__device__ ERec16 g_edata[ZZ * EE];

// ----------------- helpers -----------------
__device__ __forceinline__ float sigmoidf_(float x) { return 1.0f / (1.0f + __expf(-x)); }

__device__ __forceinline__ float tanh_approx(float x) {
    float y; asm("tanh.approx.f32 %0, %1;" : "=f"(y) : "f"(x)); return y;
}
__device__ __forceinline__ ull fma2(ull a, ull b, ull c) {
    ull d;
    asm("fma.rn.f32x2 %0, %1, %2, %3;" : "=l"(d) : "l"(a), "l"(b), "l"(c));
    return d;
}
__device__ __forceinline__ ull pack2s(float x) {
    ull u; asm("mov.b64 %0, {%1,%1};" : "=l"(u) : "f"(x)); return u;
}
__device__ __forceinline__ ull pack2f(float x, float y) {
    ull u; asm("mov.b64 %0, {%1,%2};" : "=l"(u) : "f"(x), "f"(y)); return u;
}
__device__ __forceinline__ float2 ull2f(ull u) {
    float2 v; asm("mov.b64 {%0,%1}, %2;" : "=f"(v.x), "=f"(v.y) : "l"(u)); return v;
}
__device__ __forceinline__ float2 h2f2(unsigned int bits) {
    __half2 h = *reinterpret_cast<__half2*>(&bits);
    return __half22float2(h);
}

// ================= prep mega-kernel: fold + bstack + transposes + bias + cnt-zero ==========
// blocks [0,2): fold  [2,130): bstack  [130,194): WihT  [194,258): WhhT  258: bias
// [259, 259+625): zero cnt (ZZ*NN = 160000)
#define PREP_BLOCKS (259 + 625)
__global__ __launch_bounds__(256) void prep_kernel(
    const float* __restrict__ Wsrc, const float* __restrict__ Wdst,
    const float* __restrict__ as_, const float* __restrict__ ad_,
    const float* __restrict__ Wih, const float* __restrict__ Whh,
    const float* __restrict__ bih, const float* __restrict__ bhh,
    float* __restrict__ fs, float* __restrict__ fd, float* __restrict__ Bst,
    float* __restrict__ WihT, float* __restrict__ WhhT, float* __restrict__ biassum,
    int* __restrict__ cnt) {
    int b = blockIdx.x, tid = threadIdx.x;
    if (b >= 259) {
        cnt[(b - 259) * 256 + tid] = 0;
        return;
    }
    if (b < 2) {
        int idx = b * 256 + tid;
        if (idx < RR * DD * HH) {
            int r = idx / (DD * HH);
            int k = (idx / HH) % DD;
            int h = idx % HH;
            float accs = 0.f, accd = 0.f;
            for (int c = 0; c < CC; ++c) {
                accs += Wsrc[((size_t)(r * DD + k)) * HC + h * CC + c] * as_[(r * HH + h) * CC + c];
                accd += Wdst[((size_t)(r * DD + k)) * HC + h * CC + c] * ad_[(r * HH + h) * CC + c];
            }
            fs[idx] = accs;
            fd[idx] = accd;
        }
    } else if (b < 130) {
        int idx = (b - 2) * 256 + tid;
        int r = idx / (HC * CC);
        int kk = (idx / CC) % HC;
        int co = idx % CC;
        int h = kk >> 6, ci = kk & 63;
        Bst[idx] = Wsrc[((size_t)(r * DD + ci)) * HC + h * 64 + co] * 0.25f;
    } else if (b < 194) {
        int idx = (b - 130) * 256 + tid;
        int r = idx / DD, c = idx % DD;
        WihT[c * HC + r] = Wih[idx];
    } else if (b < 258) {
        int idx = (b - 194) * 256 + tid;
        int r = idx / DD, c = idx % DD;
        WhhT[c * HC + r] = Whh[idx];
    } else {
        if (tid < HC) biassum[tid] = bih[tid] + bhh[tid];
    }
}

// ================= als + hist combined =================
#define ALS_BLOCKS 625
#define HIST_BLOCKS 10000
__global__ __launch_bounds__(256) void alshist_kernel(
    const float* __restrict__ x, const float* __restrict__ fs, const float* __restrict__ fd,
    const int* __restrict__ ei, float* __restrict__ als, float* __restrict__ ald,
    int* __restrict__ cnt) {
    int tid = threadIdx.x;
    if (blockIdx.x >= ALS_BLOCKS) {
        int i = (blockIdx.x - ALS_BLOCKS) * 256 + tid;
        int z = i / EE, e = i - z * EE;
        int dst = __ldg(ei + (size_t)z * 2 * EE + EE + e);
        atomicAdd(cnt + z * NN + dst, 1);
        return;
    }
    int idx = blockIdx.x * 256 + tid;
    int z = idx / NN, n = idx - z * NN;
    int t = z >> 1, r = z & 1;
    const float4* xr4 = reinterpret_cast<const float4*>(x + ((size_t)t * NN + n) * DD);
    const float4* fs4 = reinterpret_cast<const float4*>(fs + r * DD * HH);
    const float4* fd4 = reinterpret_cast<const float4*>(fd + r * DD * HH);
    float4 a = {0.f, 0.f, 0.f, 0.f}, b = {0.f, 0.f, 0.f, 0.f};
#pragma unroll
    for (int kk = 0; kk < 16; ++kk) {
        float4 xq = __ldg(xr4 + kk);
        float xv[4] = {xq.x, xq.y, xq.z, xq.w};
#pragma unroll
        for (int j = 0; j < 4; ++j) {
            int k = kk * 4 + j;
            float4 f = __ldg(fs4 + k);
            float4 g = __ldg(fd4 + k);
            a.x += xv[j] * f.x; a.y += xv[j] * f.y; a.z += xv[j] * f.z; a.w += xv[j] * f.w;
            b.x += xv[j] * g.x; b.y += xv[j] * g.y; b.z += xv[j] * g.z; b.w += xv[j] * g.w;
        }
    }
    reinterpret_cast<float4*>(als)[idx] = a;
    reinterpret_cast<float4*>(ald)[idx] = b;
}

// ----------------- CSR scan -----------------
__global__ __launch_bounds__(1024) void scan_kernel(const int* __restrict__ cnt,
                                                    int* __restrict__ off,
                                                    int* __restrict__ pos) {
    __shared__ int ssums[1024];
    int z = blockIdx.x;
    const int* c = cnt + z * NN;
    int* o = off + z * (NN + 1);
    int* p = pos + z * NN;
    int tid = threadIdx.x;
    const int CH = (NN + 1023) / 1024;  // 20
    int base = tid * CH;
    int s = 0;
    for (int i = 0; i < CH; ++i) {
        int idx = base + i;
        if (idx < NN) s += c[idx];
    }
    ssums[tid] = s;
    __syncthreads();
    for (int d = 1; d < 1024; d <<= 1) {
        int v = (tid >= d) ? ssums[tid - d] : 0;
        __syncthreads();
        ssums[tid] += v;
        __syncthreads();
    }
    int run = (tid > 0) ? ssums[tid - 1] : 0;
    for (int i = 0; i < CH; ++i) {
        int idx = base + i;
        if (idx < NN) {
            o[idx] = run;
            p[idx] = run;
            run += c[idx];
        }
    }
    if (tid == 1023) o[NN] = ssums[1023];
}

// scatter: per-edge softmax weights (fp16) + single 16B record store
__global__ void scatter_kernel(const int* __restrict__ ei, const float* __restrict__ als,
                               const float* __restrict__ ald, int* __restrict__ pos,
                               ERec16* __restrict__ edata) {
    int i = blockIdx.x * blockDim.x + threadIdx.x;
    if (i >= ZZ * EE) return;
    int z = i / EE, e = i - z * EE;
    int src = __ldg(ei + (size_t)z * 2 * EE + e);
    int dst = __ldg(ei + (size_t)z * 2 * EE + EE + e);
    float4 s4 = __ldg(reinterpret_cast<const float4*>(als) + (size_t)z * NN + src);
    float4 d4 = __ldg(reinterpret_cast<const float4*>(ald) + (size_t)z * NN + dst);
    float e0 = s4.x + d4.x; e0 = (e0 >= 0.f) ? e0 : 0.2f * e0;
    float e1 = s4.y + d4.y; e1 = (e1 >= 0.f) ? e1 : 0.2f * e1;
    float e2 = s4.z + d4.z; e2 = (e2 >= 0.f) ? e2 : 0.2f * e2;
    float e3 = s4.w + d4.w; e3 = (e3 >= 0.f) ? e3 : 0.2f * e3;
    __half2 h01 = __floats2half2_rn(__expf(e0), __expf(e1));
    __half2 h23 = __floats2half2_rn(__expf(e2), __expf(e3));
    int p = atomicAdd(pos + z * NN + dst, 1);
    int4 rec;
    rec.x = *reinterpret_cast<int*>(&h01);
    rec.y = *reinterpret_cast<int*>(&h23);
    rec.z = src;
    rec.w = 0;
    *reinterpret_cast<int4*>(edata + (size_t)z * EE + p) = rec;
}

// ----------------- gather: warp per (z,dst); unroll x4; 16B records, 1 LDG each ------------
__global__ __launch_bounds__(256) void gather_kernel(
    const int* __restrict__ off, const ERec16* __restrict__ edata,
    const float* __restrict__ x, float* __restrict__ agg) {
    int z = blockIdx.y;
    int d = blockIdx.x * 8 + (threadIdx.x >> 5);
    int lane = threadIdx.x & 31;
    const float* xt = x + (size_t)(z >> 1) * NN * DD;
    const int* offz = off + z * (NN + 1);
    const int4* ez = reinterpret_cast<const int4*>(edata + (size_t)z * EE);
    int i = offz[d], iend = offz[d + 1];
    ull A0 = 0ull, A1 = 0ull, A2 = 0ull, A3 = 0ull;
    ull D01 = 0ull, D23 = 0ull;
    const ull ONES = pack2s(1.0f);
    while (i + 4 <= iend) {
        int4 r0 = __ldg(ez + i);
        int4 r1 = __ldg(ez + i + 1);
        int4 r2 = __ldg(ez + i + 2);
        int4 r3 = __ldg(ez + i + 3);
        ull x0 = __ldg(reinterpret_cast<const ull*>(xt + (size_t)r0.z * DD) + lane);
        ull x1 = __ldg(reinterpret_cast<const ull*>(xt + (size_t)r1.z * DD) + lane);
        ull x2 = __ldg(reinterpret_cast<const ull*>(xt + (size_t)r2.z * DD) + lane);
        ull x3 = __ldg(reinterpret_cast<const ull*>(xt + (size_t)r3.z * DD) + lane);
        i += 4;
        float2 a01 = h2f2(r0.x), a23 = h2f2(r0.y);
        float2 b01 = h2f2(r1.x), b23 = h2f2(r1.y);
        float2 c01 = h2f2(r2.x), c23 = h2f2(r2.y);
        float2 d01v = h2f2(r3.x), d23v = h2f2(r3.y);
        D01 = fma2(pack2f(a01.x, a01.y), ONES, D01);
        D23 = fma2(pack2f(a23.x, a23.y), ONES, D23);
        A0 = fma2(pack2s(a01.x), x0, A0);
        A1 = fma2(pack2s(a01.y), x0, A1);
        A2 = fma2(pack2s(a23.x), x0, A2);
        A3 = fma2(pack2s(a23.y), x0, A3);
        D01 = fma2(pack2f(b01.x, b01.y), ONES, D01);
        D23 = fma2(pack2f(b23.x, b23.y), ONES, D23);
        A0 = fma2(pack2s(b01.x), x1, A0);
        A1 = fma2(pack2s(b01.y), x1, A1);
        A2 = fma2(pack2s(b23.x), x1, A2);
        A3 = fma2(pack2s(b23.y), x1, A3);
        D01 = fma2(pack2f(c01.x, c01.y), ONES, D01);
        D23 = fma2(pack2f(c23.x, c23.y), ONES, D23);
        A0 = fma2(pack2s(c01.x), x2, A0);
        A1 = fma2(pack2s(c01.y), x2, A1);
        A2 = fma2(pack2s(c23.x), x2, A2);
        A3 = fma2(pack2s(c23.y), x2, A3);
        D01 = fma2(pack2f(d01v.x, d01v.y), ONES, D01);
        D23 = fma2(pack2f(d23v.x, d23v.y), ONES, D23);
        A0 = fma2(pack2s(d01v.x), x3, A0);
        A1 = fma2(pack2s(d01v.y), x3, A1);
        A2 = fma2(pack2s(d23v.x), x3, A2);
        A3 = fma2(pack2s(d23v.y), x3, A3);
    }
    while (i < iend) {
        int4 r0 = __ldg(ez + i);
        ull x0 = __ldg(reinterpret_cast<const ull*>(xt + (size_t)r0.z * DD) + lane);
        ++i;
        float2 a01 = h2f2(r0.x), a23 = h2f2(r0.y);
        D01 = fma2(pack2f(a01.x, a01.y), ONES, D01);
        D23 = fma2(pack2f(a23.x, a23.y), ONES, D23);
        A0 = fma2(pack2s(a01.x), x0, A0);
        A1 = fma2(pack2s(a01.y), x0, A1);
        A2 = fma2(pack2s(a23.x), x0, A2);
        A3 = fma2(pack2s(a23.y), x0, A3);
    }
    float2 d01 = ull2f(D01), d23 = ull2f(D23);
    float i0 = 1.f / (d01.x + 1e-16f), i1 = 1.f / (d01.y + 1e-16f);
    float i2 = 1.f / (d23.x + 1e-16f), i3 = 1.f / (d23.y + 1e-16f);
    float2 a0 = ull2f(A0), a1 = ull2f(A1), a2 = ull2f(A2), a3 = ull2f(A3);
    float2* o = reinterpret_cast<float2*>(agg + ((size_t)z * NN + d) * HC) + lane;
    o[0]  = make_float2(a0.x * i0, a0.y * i0);
    o[32] = make_float2(a1.x * i1, a1.y * i1);
    o[64] = make_float2(a2.x * i2, a2.y * i2);
    o[96] = make_float2(a3.x * i3, a3.y * i3);
}

// ----------------- batched intra GEMM: 128x64 tile, 8x4/thread, k-transposed A -------------
#define GI_SMEM ((64 * 130 + 64 * 66) * 4)
__global__ __launch_bounds__(256) void gemm_intra128(const float* __restrict__ Abase,
                                                     const float* __restrict__ Bbase,
                                                     float* __restrict__ Cbase) {
    extern __shared__ float sm[];
    float* Ast = sm;            // [64 k][130]
    float* Bs = sm + 64 * 130;  // [64 k][66]
    int z = blockIdx.y;
    int tq = z >> 1, r = z & 1;
    const float* A = Abase + (size_t)z * NN * HC;
    const float* B = Bbase + (size_t)r * HC * CC;
    float* C = Cbase + (size_t)tq * NN * RR * CC + r * CC;
    int tid = threadIdx.x;
    int row0 = blockIdx.x * 128;
    int tx = tid & 15, ty = tid >> 4;
    ull acc[8][2] = {};
    for (int kc = 0; kc < HC; kc += 64) {
#pragma unroll
        for (int i = 0; i < 32; ++i) {
            int idx = tid + i * 256;
            int rr = idx >> 6, cc = idx & 63;
            int gr = row0 + rr;
            Ast[cc * 130 + rr] = (gr < NN) ? A[(size_t)gr * HC + kc + cc] : 0.f;
        }
#pragma unroll
        for (int i = 0; i < 16; ++i) {
            int idx = tid + i * 256;
            int rr = idx >> 6, cc = idx & 63;
            Bs[rr * 66 + cc] = B[(size_t)(kc + rr) * CC + cc];
        }
        __syncthreads();
#pragma unroll 8
        for (int k = 0; k < 64; ++k) {
            ull b01 = *reinterpret_cast<const ull*>(&Bs[k * 66 + tx * 4]);
            ull b23 = *reinterpret_cast<const ull*>(&Bs[k * 66 + tx * 4 + 2]);
            const float* ar = &Ast[k * 130 + ty * 8];
            float2 f01 = ull2f(*reinterpret_cast<const ull*>(ar));
            float2 f23 = ull2f(*reinterpret_cast<const ull*>(ar + 2));
            float2 f45 = ull2f(*reinterpret_cast<const ull*>(ar + 4));
            float2 f67 = ull2f(*reinterpret_cast<const ull*>(ar + 6));
            float av[8] = {f01.x, f01.y, f23.x, f23.y, f45.x, f45.y, f67.x, f67.y};
#pragma unroll
            for (int m = 0; m < 8; ++m) {
                ull am = pack2s(av[m]);
                acc[m][0] = fma2(am, b01, acc[m][0]);
                acc[m][1] = fma2(am, b23, acc[m][1]);
            }
        }
        __syncthreads();
    }
#pragma unroll
    for (int m = 0; m < 8; ++m) {
        int gr = row0 + ty * 8 + m;
        if (gr < NN) {
            float2 lo = ull2f(acc[m][0]), hi = ull2f(acc[m][1]);
            *reinterpret_cast<float4*>(C + (size_t)gr * (RR * CC) + tx * 4) =
                make_float4(lo.x, lo.y, hi.x, hi.y);
        }
    }
}

// ----------------- xg GEMM: A = beta-combined intra, K=64 -----------------
__global__ __launch_bounds__(256) void gemm_xg(
    const float* __restrict__ intra, const float* __restrict__ beta,
    const float* __restrict__ B, const float* __restrict__ bias, float* __restrict__ C) {
    __shared__ float As[64][66];
    __shared__ float Bs[64][66];
    int tid = threadIdx.x;
    int row0 = blockIdx.y * 64;
    int col0 = blockIdx.x * 64;
#pragma unroll
    for (int i = 0; i < 16; ++i) {
        int idx = tid + i * 256;
        int rr = idx >> 6, cc = idx & 63;
        int gr = row0 + rr;
        int t = gr / NN;
        size_t base = (size_t)gr * (RR * CC) + cc;
        As[rr][cc] = __ldg(beta + t * 2) * __ldg(intra + base) +
                     __ldg(beta + t * 2 + 1) * __ldg(intra + base + CC);
        Bs[rr][cc] = B[(size_t)rr * HC + col0 + cc];
    }
    __syncthreads();
    int tx = tid & 15, ty = tid >> 4;
    ull acc2[4][2] = {};
#pragma unroll 16
    for (int k = 0; k < 64; ++k) {
        ull b01 = *reinterpret_cast<const ull*>(&Bs[k][tx * 4]);
        ull b23 = *reinterpret_cast<const ull*>(&Bs[k][tx * 4 + 2]);
#pragma unroll
        for (int m = 0; m < 4; ++m) {
            ull am2 = pack2s(As[ty * 4 + m][k]);
            acc2[m][0] = fma2(am2, b01, acc2[m][0]);
            acc2[m][1] = fma2(am2, b23, acc2[m][1]);
        }
    }
#pragma unroll
    for (int m = 0; m < 4; ++m) {
        int gr = row0 + ty * 4 + m;
        float2 lo = ull2f(acc2[m][0]);
        float2 hi = ull2f(acc2[m][1]);
        int gc = col0 + tx * 4;
        float4 bv = *reinterpret_cast<const float4*>(bias + gc);
        *reinterpret_cast<float4*>(C + (size_t)gr * HC + gc) =
            make_float4(lo.x + bv.x, lo.y + bv.y, hi.x + bv.z, hi.y + bv.w);
    }
}

// ----------------- fused LSTM step: gate-striped GEMM + in-register pointwise --------------
#define LSTMF_SMEM ((64 * 66 + 64 * 258) * 4)
__global__ __launch_bounds__(256) void lstm_fused_kernel(
    const float* __restrict__ xg, const float* __restrict__ WhhT,
    float* __restrict__ lh, float* __restrict__ lc, float* __restrict__ feats,
    int t, int first) {
    extern __shared__ float sm[];
    float* As = sm;            // [64][66]
    float* Bs = sm + 64 * 66;  // [64][258]
    int tid = threadIdx.x;
    int row0 = blockIdx.x * 64;
    int tx = tid & 15, ty = tid >> 4;
    ull acc[4][8] = {};
    if (!first) {
#pragma unroll
        for (int i = 0; i < 16; ++i) {
            int idx = tid + i * 256;
            int rr = idx >> 6, cc = idx & 63;
            int gn = row0 + rr;
            As[rr * 66 + cc] = (gn < NN) ? lh[(size_t)gn * 64 + cc] : 0.f;
        }
#pragma unroll
        for (int i = 0; i < 64; ++i) {
            int idx = tid + i * 256;
            int k = idx >> 8, g = idx & 255;
            Bs[k * 258 + g] = WhhT[idx];
        }
        __syncthreads();
#pragma unroll 8
        for (int k = 0; k < 64; ++k) {
            ull b[8];
#pragma unroll
            for (int g = 0; g < 4; ++g) {
                b[g * 2] = *reinterpret_cast<const ull*>(&Bs[k * 258 + g * 64 + tx * 4]);
                b[g * 2 + 1] = *reinterpret_cast<const ull*>(&Bs[k * 258 + g * 64 + tx * 4 + 2]);
            }
#pragma unroll
            for (int m = 0; m < 4; ++m) {
                ull a2 = pack2s(As[(ty * 4 + m) * 66 + k]);
#pragma unroll
                for (int j = 0; j < 8; ++j) acc[m][j] = fma2(a2, b[j], acc[m][j]);
            }
        }
    }
#pragma unroll
    for (int m = 0; m < 4; ++m) {
        int gn = row0 + ty * 4 + m;
        if (gn >= NN) continue;
        float gv[4][4];
#pragma unroll
        for (int g = 0; g < 4; ++g) {
            float2 lo = ull2f(acc[m][g * 2]);
            float2 hi = ull2f(acc[m][g * 2 + 1]);
            float4 xv = *reinterpret_cast<const float4*>(
                xg + ((size_t)t * NN + gn) * HC + g * 64 + tx * 4);
            gv[g][0] = lo.x + xv.x; gv[g][1] = lo.y + xv.y;
            gv[g][2] = hi.x + xv.z; gv[g][3] = hi.y + xv.w;
        }
        float cp[4] = {0.f, 0.f, 0.f, 0.f};
        if (!first) {
            float4 cprev = *reinterpret_cast<const float4*>(lc + (size_t)gn * 64 + tx * 4);
            cp[0] = cprev.x; cp[1] = cprev.y; cp[2] = cprev.z; cp[3] = cprev.w;
        }
        float cn[4], hn[4];
#pragma unroll
        for (int o = 0; o < 4; ++o) {
            float ci = sigmoidf_(gv[1][o]) * cp[o] + sigmoidf_(gv[0][o]) * tanhf(gv[2][o]);
            cn[o] = ci;
            hn[o] = sigmoidf_(gv[3][o]) * tanhf(ci);
        }
        *reinterpret_cast<float4*>(lc + (size_t)gn * 64 + tx * 4) =
            make_float4(cn[0], cn[1], cn[2], cn[3]);
        *reinterpret_cast<float4*>(lh + (size_t)gn * 64 + tx * 4) =
            make_float4(hn[0], hn[1], hn[2], hn[3]);
        *reinterpret_cast<float4*>(feats + ((size_t)gn * TT + t) * 64 + tx * 4) =
            make_float4(hn[0], hn[1], hn[2], hn[3]);
    }
}

// ----------------- relation scores: 4 rows per warp iteration -----------------
__global__ __launch_bounds__(256) void relation_kernel(
    const float* __restrict__ hmat, const float* __restrict__ W1,
    const float* __restrict__ b1, const float* __restrict__ W2,
    float* __restrict__ ssum) {
    extern __shared__ float sm[];
    float2* sW1v = reinterpret_cast<float2*>(sm);  // 8192 float2
    float* sb1 = sm + 16384;
    float* sW2 = sm + 16640;
    float* sbins = sm + 16896;
    int tid = threadIdx.x;
    for (int i = tid; i < 8192; i += 256) {
        int k = i >> 7;
        int rem = i & 127;
        int p = rem >> 5, l = rem & 31;
        int j1 = k * 256 + p * 64 + l;
        sW1v[i] = make_float2(W1[j1], W1[j1 + 32]);
    }
    if (tid < 256) { sb1[tid] = b1[tid]; sW2[tid] = W2[tid]; }
    if (tid < TT * RR) sbins[tid] = 0.f;
    __syncthreads();
    int lane = tid & 31;
    int gw = (blockIdx.x * blockDim.x + tid) >> 5;
    int nwarps = (gridDim.x * blockDim.x) >> 5;
    const int groups = (TT * NN * RR) / 4;  // 40000
    const int NR = NN * RR;
    const ull* wbase = reinterpret_cast<const ull*>(sW1v) + lane;
    for (int g = gw; g < groups; g += nwarps) {
        int row = g * 4;
        const float* hr = hmat + (size_t)row * CC;
        float h0[4], h1[4];
#pragma unroll
        for (int j = 0; j < 4; ++j) {
            h0[j] = hr[j * 64 + lane];
            h1[j] = hr[j * 64 + lane + 32];
        }
        ull a2[4][4] = {};
#pragma unroll 4
        for (int k = 0; k < 32; ++k) {
            const ull* w = wbase + k * 128;
            ull w0 = w[0], w1 = w[32], w2 = w[64], w3 = w[96];
#pragma unroll
            for (int j = 0; j < 4; ++j) {
                ull hk2 = pack2s(__shfl_sync(0xffffffffu, h0[j], k));
                a2[j][0] = fma2(hk2, w0, a2[j][0]);
                a2[j][1] = fma2(hk2, w1, a2[j][1]);
                a2[j][2] = fma2(hk2, w2, a2[j][2]);
                a2[j][3] = fma2(hk2, w3, a2[j][3]);
            }
        }
#pragma unroll 4
        for (int k = 0; k < 32; ++k) {
            const ull* w = wbase + (k + 32) * 128;
            ull w0 = w[0], w1 = w[32], w2 = w[64], w3 = w[96];
#pragma unroll
            for (int j = 0; j < 4; ++j) {
                ull hk2 = pack2s(__shfl_sync(0xffffffffu, h1[j], k));
                a2[j][0] = fma2(hk2, w0, a2[j][0]);
                a2[j][1] = fma2(hk2, w1, a2[j][1]);
                a2[j][2] = fma2(hk2, w2, a2[j][2]);
                a2[j][3] = fma2(hk2, w3, a2[j][3]);
            }
        }
        float acc[4];
#pragma unroll
        for (int j = 0; j < 4; ++j) {
            float s = 0.f;
#pragma unroll
            for (int p = 0; p < 4; ++p) {
                float2 av = ull2f(a2[j][p]);
                int j1 = p * 64 + lane, j2 = j1 + 32;
                s += tanh_approx(av.x + sb1[j1]) * sW2[j1];
                s += tanh_approx(av.y + sb1[j2]) * sW2[j2];
            }
            acc[j] = s;
        }
        float accA = acc[0] + acc[2];
        float accB = acc[1] + acc[3];
#pragma unroll
        for (int off2 = 16; off2 > 0; off2 >>= 1) {
            accA += __shfl_down_sync(0xffffffffu, accA, off2);
            accB += __shfl_down_sync(0xffffffffu, accB, off2);
        }
        if (lane == 0) {
            int binb = (row / NR) * RR;
            atomicAdd(&sbins[binb], accA);
            atomicAdd(&sbins[binb + 1], accB);
        }
    }
    __syncthreads();
    if (tid < TT * RR) atomicAdd(&ssum[tid], sbins[tid]);
}

__global__ void beta_kernel(const float* __restrict__ ssum, float* __restrict__ beta) {
    int t = threadIdx.x;
    if (t < TT) {
        float s0 = ssum[t * RR + 0] * (1.0f / NN);
        float s1 = ssum[t * RR + 1] * (1.0f / NN);
        float m = fmaxf(s0, s1);
        float e0 = expf(s0 - m), e1 = expf(s1 - m);
        float inv = 1.f / (e0 + e1);
        beta[t * RR + 0] = e0 * inv;
        beta[t * RR + 1] = e1 * inv;
    }
}

// ----------------- temporal multi-head attention: warp handles 2 nodes -----------------
__global__ __launch_bounds__(256) void attn_kernel(
    const float* __restrict__ feats, const float* __restrict__ pos,
    const float* __restrict__ Wq, const float* __restrict__ Wk, const float* __restrict__ Wv,
    float* __restrict__ out) {
    extern __shared__ float sm[];
    float* sWq = sm;
    float* sWk = sm + 4096;
    float* sWv = sm + 8192;
    float* spos = sm + 12288;
    float* wb = sm + 12544;
    int tid = threadIdx.x;
    for (int i = tid; i < 4096; i += 256) {
        sWq[i] = Wq[i]; sWk[i] = Wk[i]; sWv[i] = Wv[i];
    }
    if (tid < 256) spos[tid] = pos[tid];
    __syncthreads();
    int wid = tid >> 5, lane = tid & 31;
    int nbase = blockIdx.x * 8 + wid;
    float* ti = wb + wid * 1088;
    float* q = ti + 256;
    float* k_ = q + 256;
    float* v = k_ + 256;
    float* a = v + 256;
#pragma unroll
    for (int rep = 0; rep < 2; ++rep) {
        int n = nbase + rep * (NN / 2);
#pragma unroll
        for (int m = 0; m < 8; ++m) {
            int o = m * 32 + lane;
            ti[o] = feats[(size_t)n * 256 + o] + spos[o];
        }
        __syncwarp();
        {
            const ull* wq64 = reinterpret_cast<const ull*>(sWq);
            const ull* wk64 = reinterpret_cast<const ull*>(sWk);
            const ull* wv64 = reinterpret_cast<const ull*>(sWv);
            ull q2[4] = {}, k2[4] = {}, v2[4] = {};
#pragma unroll 4
            for (int k = 0; k < 64; ++k) {
                ull wq = wq64[k * 32 + lane];
                ull wk = wk64[k * 32 + lane];
                ull wv = wv64[k * 32 + lane];
#pragma unroll
                for (int t = 0; t < 4; ++t) {
                    ull tv = pack2s(ti[t * 64 + k]);
                    q2[t] = fma2(tv, wq, q2[t]);
                    k2[t] = fma2(tv, wk, k2[t]);
                    v2[t] = fma2(tv, wv, v2[t]);
                }
            }
#pragma unroll
            for (int t = 0; t < 4; ++t) {
                reinterpret_cast<float2*>(q)[t * 32 + lane] = ull2f(q2[t]);
                reinterpret_cast<float2*>(k_)[t * 32 + lane] = ull2f(k2[t]);
                reinterpret_cast<float2*>(v)[t * 32 + lane] = ull2f(v2[t]);
            }
        }
        __syncwarp();
        if (lane < 16) {
            int h = lane >> 2, tq = lane & 3;
            float sc[4];
            for (int tk = 0; tk <= tq; ++tk) {
                float s = 0.f;
#pragma unroll
                for (int ch = 0; ch < 16; ++ch)
                    s += q[tq * 64 + h * 16 + ch] * k_[tk * 64 + h * 16 + ch];
                sc[tk] = s * 0.5f;
            }
            float mx = sc[0];
            for (int tk = 1; tk <= tq; ++tk) mx = fmaxf(mx, sc[tk]);
            float sum = 0.f;
            for (int tk = 0; tk <= tq; ++tk) { sc[tk] = __expf(sc[tk] - mx); sum += sc[tk]; }
            float inv = 1.f / sum;
            for (int tk = 0; tk < 4; ++tk)
                a[h * 16 + tq * 4 + tk] = (tk <= tq) ? sc[tk] * inv : 0.f;
        }
        __syncwarp();
        {
            int h = lane >> 3;
            const ull* v64 = reinterpret_cast<const ull*>(v);
#pragma unroll
            for (int tq = 0; tq < 4; ++tq) {
                ull acc = 0ull;
#pragma unroll
                for (int tk = 0; tk < 4; ++tk)
                    acc = fma2(pack2s(a[h * 16 + tq * 4 + tk]), v64[tk * 32 + lane], acc);
                reinterpret_cast<float2*>(out + (size_t)n * 256 + tq * 64)[lane] = ull2f(acc);
            }
        }
        __syncwarp();
    }
}

// ----------------- host launch -----------------
template <typename T>
static T* symaddr(const void* sym) {
    void* p = nullptr;
    cudaGetSymbolAddress(&p, sym);
    return (T*)p;
}

extern "C" void kernel_launch(void* const* d_in, const int* in_sizes, int n_in,
                              void* d_out, int out_size) {
    const float* x = (const float*)d_in[0];
    const int* ei = (const int*)d_in[1];
    const float* W_src = (const float*)d_in[2];
    const float* W_dst = (const float*)d_in[3];
    const float* att_src = (const float*)d_in[4];
    const float* att_dst = (const float*)d_in[5];
    const float* ra_W1 = (const float*)d_in[6];
    const float* ra_b1 = (const float*)d_in[7];
    const float* ra_W2 = (const float*)d_in[8];
    const float* Wih = (const float*)d_in[9];
    const float* Whh = (const float*)d_in[10];
    const float* bih = (const float*)d_in[11];
    const float* bhh = (const float*)d_in[12];
    const float* pos = (const float*)d_in[13];
    const float* Wq = (const float*)d_in[14];
    const float* Wk = (const float*)d_in[15];
    const float* Wv = (const float*)d_in[16];
    float* out = (float*)d_out;

    float* agg = symaddr<float>(g_agg);
    float* als = symaddr<float>(g_als);
    float* ald = symaddr<float>(g_ald);
    float* intra = symaddr<float>(g_intra);
    float* ssum = symaddr<float>(g_ssum);
    float* beta = symaddr<float>(g_beta);
    float* xg = symaddr<float>(g_xg);
    float* lh = symaddr<float>(g_lh);
    float* lc = symaddr<float>(g_lc);
    float* feats = symaddr<float>(g_feats);
    float* WihT = symaddr<float>(g_WihT);
    float* WhhT = symaddr<float>(g_WhhT);
    float* biassum = symaddr<float>(g_biassum);
    float* folds = symaddr<float>(g_folds);
    float* foldd = symaddr<float>(g_foldd);
    float* Bstack = symaddr<float>(g_Bstack);
    int* cnt = symaddr<int>(g_cnt);
    int* off = symaddr<int>(g_off);
    int* posb = symaddr<int>(g_pos);
    ERec16* edata = symaddr<ERec16>(g_edata);

    const int REL_SMEM = (16384 + 256 + 256 + 8) * 4;
    const int ATT_SMEM = (12544 + 8 * 1088) * 4;
    cudaFuncSetAttribute(relation_kernel, cudaFuncAttributeMaxDynamicSharedMemorySize, REL_SMEM);
    cudaFuncSetAttribute(attn_kernel, cudaFuncAttributeMaxDynamicSharedMemorySize, ATT_SMEM);
    cudaFuncSetAttribute(gemm_intra128, cudaFuncAttributeMaxDynamicSharedMemorySize, GI_SMEM);
    cudaFuncSetAttribute(lstm_fused_kernel, cudaFuncAttributeMaxDynamicSharedMemorySize,
                         LSTMF_SMEM);

    // ---- prep (cnt zeroing fused in) + CSR/GAT front
    prep_kernel<<<PREP_BLOCKS, 256>>>(W_src, W_dst, att_src, att_dst, Wih, Whh, bih, bhh,
                                      folds, foldd, Bstack, WihT, WhhT, biassum, cnt);
    alshist_kernel<<<ALS_BLOCKS + HIST_BLOCKS, 256>>>(x, folds, foldd, ei, als, ald, cnt);
    scan_kernel<<<ZZ, 1024>>>(cnt, off, posb);
    scatter_kernel<<<(ZZ * EE) / 256, 256>>>(ei, als, ald, posb, edata);
    gather_kernel<<<dim3(NN / 8, ZZ), 256>>>(off, edata, x, agg);

    // ---- batched intra GEMM (128-row tiles)
    gemm_intra128<<<dim3((NN + 127) / 128, ZZ), 256, GI_SMEM>>>(agg, Bstack, intra);

    // ---- relation aggregation
    cudaMemsetAsync(ssum, 0, TT * RR * sizeof(float), 0);
    relation_kernel<<<444, 256, REL_SMEM>>>(intra, ra_W1, ra_b1, ra_W2, ssum);
    beta_kernel<<<1, 32>>>(ssum, beta);

    // ---- LSTM: beta-fused xg GEMM, then per-step fused kernels (t=0 specialized)
    gemm_xg<<<dim3(HC / 64, (TT * NN) / 64), 256>>>(intra, beta, WihT, biassum, xg);
    for (int t = 0; t < TT; ++t) {
        lstm_fused_kernel<<<(NN + 63) / 64, 256, LSTMF_SMEM>>>(xg, WhhT, lh, lc, feats, t,
                                                               t == 0 ? 1 : 0);
    }

    // ---- temporal attention
    attn_kernel<<<(NN + 15) / 16, 256, ATT_SMEM>>>(feats, pos, Wq, Wk, Wv, out);
}

// round 12
// speedup vs baseline: 1.0317x; 1.0317x over previous
#include <cuda_runtime.h>
#include <cuda_fp16.h>
#include <math.h>
#include <stdint.h>

#define TT 4
#define NN 20000
#define EE 320000
#define RR 2
#define DD 64
#define HH 4
#define CC 64
#define HC 256   // H*C
#define ZZ 8     // T*R

typedef unsigned long long ull;

// ----------------- scratch (static device globals; no allocation) -----------------
__device__ __align__(16) float g_agg[ZZ * NN * HC];
__device__ __align__(16) float g_als[ZZ * NN * HH];
__device__ __align__(16) float g_ald[ZZ * NN * HH];
__device__ __align__(16) float g_intra[TT * NN * RR * CC];
__device__ float g_ssum[TT * RR];
__device__ float g_beta[TT * RR];
__device__ __align__(16) float g_xg[TT * NN * HC];
__device__ __align__(16) float g_lh[NN * CC];
__device__ __align__(16) float g_lc[NN * CC];
__device__ __align__(16) float g_feats[NN * TT * CC];
__device__ float g_WihT[DD * HC];
__device__ float g_WhhT[DD * HC];
__device__ float g_biassum[HC];
__device__ __align__(16) float g_folds[RR * DD * HH];
__device__ __align__(16) float g_foldd[RR * DD * HH];
__device__ float g_Bstack[RR * HC * CC];
__device__ int g_cnt[ZZ * NN];
__device__ int g_off[ZZ * (NN + 1)];
__device__ int g_pos[ZZ * NN];
__device__ int g_sorted[ZZ * EE];        // dense 4B/edge src stream (gather critical path)
__device__ __align__(8) ull g_wsort8[ZZ * EE];  // half4 weights, 8B/edge

// ----------------- helpers -----------------
__device__ __forceinline__ float sigmoidf_(float x) { return 1.0f / (1.0f + __expf(-x)); }

__device__ __forceinline__ float tanh_approx(float x) {
    float y; asm("tanh.approx.f32 %0, %1;" : "=f"(y) : "f"(x)); return y;
}
__device__ __forceinline__ ull fma2(ull a, ull b, ull c) {
    ull d;
    asm("fma.rn.f32x2 %0, %1, %2, %3;" : "=l"(d) : "l"(a), "l"(b), "l"(c));
    return d;
}
__device__ __forceinline__ ull pack2s(float x) {
    ull u; asm("mov.b64 %0, {%1,%1};" : "=l"(u) : "f"(x)); return u;
}
__device__ __forceinline__ ull pack2f(float x, float y) {
    ull u; asm("mov.b64 %0, {%1,%2};" : "=l"(u) : "f"(x), "f"(y)); return u;
}
__device__ __forceinline__ float2 ull2f(ull u) {
    float2 v; asm("mov.b64 {%0,%1}, %2;" : "=f"(v.x), "=f"(v.y) : "l"(u)); return v;
}
__device__ __forceinline__ float2 h2f2(unsigned int bits) {
    __half2 h = *reinterpret_cast<__half2*>(&bits);
    return __half22float2(h);
}

// ================= prep mega-kernel: fold + bstack + transposes + bias + cnt-zero ==========
#define PREP_BLOCKS (259 + 625)
__global__ __launch_bounds__(256) void prep_kernel(
    const float* __restrict__ Wsrc, const float* __restrict__ Wdst,
    const float* __restrict__ as_, const float* __restrict__ ad_,
    const float* __restrict__ Wih, const float* __restrict__ Whh,
    const float* __restrict__ bih, const float* __restrict__ bhh,
    float* __restrict__ fs, float* __restrict__ fd, float* __restrict__ Bst,
    float* __restrict__ WihT, float* __restrict__ WhhT, float* __restrict__ biassum,
    int* __restrict__ cnt) {
    int b = blockIdx.x, tid = threadIdx.x;
    if (b >= 259) {
        cnt[(b - 259) * 256 + tid] = 0;
        return;
    }
    if (b < 2) {
        int idx = b * 256 + tid;
        if (idx < RR * DD * HH) {
            int r = idx / (DD * HH);
            int k = (idx / HH) % DD;
            int h = idx % HH;
            float accs = 0.f, accd = 0.f;
            for (int c = 0; c < CC; ++c) {
                accs += Wsrc[((size_t)(r * DD + k)) * HC + h * CC + c] * as_[(r * HH + h) * CC + c];
                accd += Wdst[((size_t)(r * DD + k)) * HC + h * CC + c] * ad_[(r * HH + h) * CC + c];
            }
            fs[idx] = accs;
            fd[idx] = accd;
        }
    } else if (b < 130) {
        int idx = (b - 2) * 256 + tid;
        int r = idx / (HC * CC);
        int kk = (idx / CC) % HC;
        int co = idx % CC;
        int h = kk >> 6, ci = kk & 63;
        Bst[idx] = Wsrc[((size_t)(r * DD + ci)) * HC + h * 64 + co] * 0.25f;
    } else if (b < 194) {
        int idx = (b - 130) * 256 + tid;
        int r = idx / DD, c = idx % DD;
        WihT[c * HC + r] = Wih[idx];
    } else if (b < 258) {
        int idx = (b - 194) * 256 + tid;
        int r = idx / DD, c = idx % DD;
        WhhT[c * HC + r] = Whh[idx];
    } else {
        if (tid < HC) biassum[tid] = bih[tid] + bhh[tid];
    }
}

// ================= als + hist combined =================
#define ALS_BLOCKS 625
#define HIST_BLOCKS 10000
__global__ __launch_bounds__(256) void alshist_kernel(
    const float* __restrict__ x, const float* __restrict__ fs, const float* __restrict__ fd,
    const int* __restrict__ ei, float* __restrict__ als, float* __restrict__ ald,
    int* __restrict__ cnt) {
    int tid = threadIdx.x;
    if (blockIdx.x >= ALS_BLOCKS) {
        int i = (blockIdx.x - ALS_BLOCKS) * 256 + tid;
        int z = i / EE, e = i - z * EE;
        int dst = __ldg(ei + (size_t)z * 2 * EE + EE + e);
        atomicAdd(cnt + z * NN + dst, 1);
        return;
    }
    int idx = blockIdx.x * 256 + tid;
    int z = idx / NN, n = idx - z * NN;
    int t = z >> 1, r = z & 1;
    const float4* xr4 = reinterpret_cast<const float4*>(x + ((size_t)t * NN + n) * DD);
    const float4* fs4 = reinterpret_cast<const float4*>(fs + r * DD * HH);
    const float4* fd4 = reinterpret_cast<const float4*>(fd + r * DD * HH);
    float4 a = {0.f, 0.f, 0.f, 0.f}, b = {0.f, 0.f, 0.f, 0.f};
#pragma unroll
    for (int kk = 0; kk < 16; ++kk) {
        float4 xq = __ldg(xr4 + kk);
        float xv[4] = {xq.x, xq.y, xq.z, xq.w};
#pragma unroll
        for (int j = 0; j < 4; ++j) {
            int k = kk * 4 + j;
            float4 f = __ldg(fs4 + k);
            float4 g = __ldg(fd4 + k);
            a.x += xv[j] * f.x; a.y += xv[j] * f.y; a.z += xv[j] * f.z; a.w += xv[j] * f.w;
            b.x += xv[j] * g.x; b.y += xv[j] * g.y; b.z += xv[j] * g.z; b.w += xv[j] * g.w;
        }
    }
    reinterpret_cast<float4*>(als)[idx] = a;
    reinterpret_cast<float4*>(ald)[idx] = b;
}

// ----------------- CSR scan -----------------
__global__ __launch_bounds__(1024) void scan_kernel(const int* __restrict__ cnt,
                                                    int* __restrict__ off,
                                                    int* __restrict__ pos) {
    __shared__ int ssums[1024];
    int z = blockIdx.x;
    const int* c = cnt + z * NN;
    int* o = off + z * (NN + 1);
    int* p = pos + z * NN;
    int tid = threadIdx.x;
    const int CH = (NN + 1023) / 1024;  // 20
    int base = tid * CH;
    int s = 0;
    for (int i = 0; i < CH; ++i) {
        int idx = base + i;
        if (idx < NN) s += c[idx];
    }
    ssums[tid] = s;
    __syncthreads();
    for (int d = 1; d < 1024; d <<= 1) {
        int v = (tid >= d) ? ssums[tid - d] : 0;
        __syncthreads();
        ssums[tid] += v;
        __syncthreads();
    }
    int run = (tid > 0) ? ssums[tid - 1] : 0;
    for (int i = 0; i < CH; ++i) {
        int idx = base + i;
        if (idx < NN) {
            o[idx] = run;
            p[idx] = run;
            run += c[idx];
        }
    }
    if (tid == 1023) o[NN] = ssums[1023];
}

// scatter: per-edge softmax weights (half4, 8B) + dense 4B src stream
__global__ void scatter_kernel(const int* __restrict__ ei, const float* __restrict__ als,
                               const float* __restrict__ ald, int* __restrict__ pos,
                               int* __restrict__ sorted, ull* __restrict__ wsort8) {
    int i = blockIdx.x * blockDim.x + threadIdx.x;
    if (i >= ZZ * EE) return;
    int z = i / EE, e = i - z * EE;
    int src = __ldg(ei + (size_t)z * 2 * EE + e);
    int dst = __ldg(ei + (size_t)z * 2 * EE + EE + e);
    float4 s4 = __ldg(reinterpret_cast<const float4*>(als) + (size_t)z * NN + src);
    float4 d4 = __ldg(reinterpret_cast<const float4*>(ald) + (size_t)z * NN + dst);
    float e0 = s4.x + d4.x; e0 = (e0 >= 0.f) ? e0 : 0.2f * e0;
    float e1 = s4.y + d4.y; e1 = (e1 >= 0.f) ? e1 : 0.2f * e1;
    float e2 = s4.z + d4.z; e2 = (e2 >= 0.f) ? e2 : 0.2f * e2;
    float e3 = s4.w + d4.w; e3 = (e3 >= 0.f) ? e3 : 0.2f * e3;
    __half2 h01 = __floats2half2_rn(__expf(e0), __expf(e1));
    __half2 h23 = __floats2half2_rn(__expf(e2), __expf(e3));
    unsigned int u01 = *reinterpret_cast<unsigned int*>(&h01);
    unsigned int u23 = *reinterpret_cast<unsigned int*>(&h23);
    ull w8 = (ull)u01 | ((ull)u23 << 32);
    int p = atomicAdd(pos + z * NN + dst, 1);
    sorted[(size_t)z * EE + p] = src;
    wsort8[(size_t)z * EE + p] = w8;
}

// ----------------- gather: warp per (z,dst); unroll x4; dense src + 8B weights -------------
__global__ __launch_bounds__(256) void gather_kernel(
    const int* __restrict__ off, const int* __restrict__ sorted,
    const ull* __restrict__ wsort8, const float* __restrict__ x,
    float* __restrict__ agg) {
    int z = blockIdx.y;
    int d = blockIdx.x * 8 + (threadIdx.x >> 5);
    int lane = threadIdx.x & 31;
    const float* xt = x + (size_t)(z >> 1) * NN * DD;
    const int* offz = off + z * (NN + 1);
    const int* sz = sorted + (size_t)z * EE;
    const ull* wz = wsort8 + (size_t)z * EE;
    int i = offz[d], iend = offz[d + 1];
    ull A0 = 0ull, A1 = 0ull, A2 = 0ull, A3 = 0ull;
    ull D01 = 0ull, D23 = 0ull;
    const ull ONES = pack2s(1.0f);
    while (i + 4 <= iend) {
        int s0 = __ldg(sz + i);
        int s1 = __ldg(sz + i + 1);
        int s2 = __ldg(sz + i + 2);
        int s3 = __ldg(sz + i + 3);
        ull w0 = __ldg(wz + i);
        ull w1 = __ldg(wz + i + 1);
        ull w2 = __ldg(wz + i + 2);
        ull w3 = __ldg(wz + i + 3);
        ull x0 = __ldg(reinterpret_cast<const ull*>(xt + (size_t)s0 * DD) + lane);
        ull x1 = __ldg(reinterpret_cast<const ull*>(xt + (size_t)s1 * DD) + lane);
        ull x2 = __ldg(reinterpret_cast<const ull*>(xt + (size_t)s2 * DD) + lane);
        ull x3 = __ldg(reinterpret_cast<const ull*>(xt + (size_t)s3 * DD) + lane);
        i += 4;
        float2 a01 = h2f2((unsigned int)w0), a23 = h2f2((unsigned int)(w0 >> 32));
        float2 b01 = h2f2((unsigned int)w1), b23 = h2f2((unsigned int)(w1 >> 32));
        float2 c01 = h2f2((unsigned int)w2), c23 = h2f2((unsigned int)(w2 >> 32));
        float2 d01v = h2f2((unsigned int)w3), d23v = h2f2((unsigned int)(w3 >> 32));
        D01 = fma2(pack2f(a01.x, a01.y), ONES, D01);
        D23 = fma2(pack2f(a23.x, a23.y), ONES, D23);
        A0 = fma2(pack2s(a01.x), x0, A0);
        A1 = fma2(pack2s(a01.y), x0, A1);
        A2 = fma2(pack2s(a23.x), x0, A2);
        A3 = fma2(pack2s(a23.y), x0, A3);
        D01 = fma2(pack2f(b01.x, b01.y), ONES, D01);
        D23 = fma2(pack2f(b23.x, b23.y), ONES, D23);
        A0 = fma2(pack2s(b01.x), x1, A0);
        A1 = fma2(pack2s(b01.y), x1, A1);
        A2 = fma2(pack2s(b23.x), x1, A2);
        A3 = fma2(pack2s(b23.y), x1, A3);
        D01 = fma2(pack2f(c01.x, c01.y), ONES, D01);
        D23 = fma2(pack2f(c23.x, c23.y), ONES, D23);
        A0 = fma2(pack2s(c01.x), x2, A0);
        A1 = fma2(pack2s(c01.y), x2, A1);
        A2 = fma2(pack2s(c23.x), x2, A2);
        A3 = fma2(pack2s(c23.y), x2, A3);
        D01 = fma2(pack2f(d01v.x, d01v.y), ONES, D01);
        D23 = fma2(pack2f(d23v.x, d23v.y), ONES, D23);
        A0 = fma2(pack2s(d01v.x), x3, A0);
        A1 = fma2(pack2s(d01v.y), x3, A1);
        A2 = fma2(pack2s(d23v.x), x3, A2);
        A3 = fma2(pack2s(d23v.y), x3, A3);
    }
    while (i < iend) {
        int s0 = __ldg(sz + i);
        ull w0 = __ldg(wz + i);
        ull x0 = __ldg(reinterpret_cast<const ull*>(xt + (size_t)s0 * DD) + lane);
        ++i;
        float2 a01 = h2f2((unsigned int)w0), a23 = h2f2((unsigned int)(w0 >> 32));
        D01 = fma2(pack2f(a01.x, a01.y), ONES, D01);
        D23 = fma2(pack2f(a23.x, a23.y), ONES, D23);
        A0 = fma2(pack2s(a01.x), x0, A0);
        A1 = fma2(pack2s(a01.y), x0, A1);
        A2 = fma2(pack2s(a23.x), x0, A2);
        A3 = fma2(pack2s(a23.y), x0, A3);
    }
    float2 d01 = ull2f(D01), d23 = ull2f(D23);
    float i0 = 1.f / (d01.x + 1e-16f), i1 = 1.f / (d01.y + 1e-16f);
    float i2 = 1.f / (d23.x + 1e-16f), i3 = 1.f / (d23.y + 1e-16f);
    float2 a0 = ull2f(A0), a1 = ull2f(A1), a2 = ull2f(A2), a3 = ull2f(A3);
    float2* o = reinterpret_cast<float2*>(agg + ((size_t)z * NN + d) * HC) + lane;
    o[0]  = make_float2(a0.x * i0, a0.y * i0);
    o[32] = make_float2(a1.x * i1, a1.y * i1);
    o[64] = make_float2(a2.x * i2, a2.y * i2);
    o[96] = make_float2(a3.x * i3, a3.y * i3);
}

// ----------------- batched intra GEMM: 128x64 tile, 8x4/thread, k-transposed A -------------
#define GI_SMEM ((64 * 130 + 64 * 66) * 4)
__global__ __launch_bounds__(256) void gemm_intra128(const float* __restrict__ Abase,
                                                     const float* __restrict__ Bbase,
                                                     float* __restrict__ Cbase) {
    extern __shared__ float sm[];
    float* Ast = sm;            // [64 k][130]
    float* Bs = sm + 64 * 130;  // [64 k][66]
    int z = blockIdx.y;
    int tq = z >> 1, r = z & 1;
    const float* A = Abase + (size_t)z * NN * HC;
    const float* B = Bbase + (size_t)r * HC * CC;
    float* C = Cbase + (size_t)tq * NN * RR * CC + r * CC;
    int tid = threadIdx.x;
    int row0 = blockIdx.x * 128;
    int tx = tid & 15, ty = tid >> 4;
    ull acc[8][2] = {};
    for (int kc = 0; kc < HC; kc += 64) {
#pragma unroll
        for (int i = 0; i < 32; ++i) {
            int idx = tid + i * 256;
            int rr = idx >> 6, cc = idx & 63;
            int gr = row0 + rr;
            Ast[cc * 130 + rr] = (gr < NN) ? A[(size_t)gr * HC + kc + cc] : 0.f;
        }
#pragma unroll
        for (int i = 0; i < 16; ++i) {
            int idx = tid + i * 256;
            int rr = idx >> 6, cc = idx & 63;
            Bs[rr * 66 + cc] = B[(size_t)(kc + rr) * CC + cc];
        }
        __syncthreads();
#pragma unroll 8
        for (int k = 0; k < 64; ++k) {
            ull b01 = *reinterpret_cast<const ull*>(&Bs[k * 66 + tx * 4]);
            ull b23 = *reinterpret_cast<const ull*>(&Bs[k * 66 + tx * 4 + 2]);
            const float* ar = &Ast[k * 130 + ty * 8];
            float2 f01 = ull2f(*reinterpret_cast<const ull*>(ar));
            float2 f23 = ull2f(*reinterpret_cast<const ull*>(ar + 2));
            float2 f45 = ull2f(*reinterpret_cast<const ull*>(ar + 4));
            float2 f67 = ull2f(*reinterpret_cast<const ull*>(ar + 6));
            float av[8] = {f01.x, f01.y, f23.x, f23.y, f45.x, f45.y, f67.x, f67.y};
#pragma unroll
            for (int m = 0; m < 8; ++m) {
                ull am = pack2s(av[m]);
                acc[m][0] = fma2(am, b01, acc[m][0]);
                acc[m][1] = fma2(am, b23, acc[m][1]);
            }
        }
        __syncthreads();
    }
#pragma unroll
    for (int m = 0; m < 8; ++m) {
        int gr = row0 + ty * 8 + m;
        if (gr < NN) {
            float2 lo = ull2f(acc[m][0]), hi = ull2f(acc[m][1]);
            *reinterpret_cast<float4*>(C + (size_t)gr * (RR * CC) + tx * 4) =
                make_float4(lo.x, lo.y, hi.x, hi.y);
        }
    }
}

// ----------------- xg GEMM: A = beta-combined intra, K=64 -----------------
__global__ __launch_bounds__(256) void gemm_xg(
    const float* __restrict__ intra, const float* __restrict__ beta,
    const float* __restrict__ B, const float* __restrict__ bias, float* __restrict__ C) {
    __shared__ float As[64][66];
    __shared__ float Bs[64][66];
    int tid = threadIdx.x;
    int row0 = blockIdx.y * 64;
    int col0 = blockIdx.x * 64;
#pragma unroll
    for (int i = 0; i < 16; ++i) {
        int idx = tid + i * 256;
        int rr = idx >> 6, cc = idx & 63;
        int gr = row0 + rr;
        int t = gr / NN;
        size_t base = (size_t)gr * (RR * CC) + cc;
        As[rr][cc] = __ldg(beta + t * 2) * __ldg(intra + base) +
                     __ldg(beta + t * 2 + 1) * __ldg(intra + base + CC);
        Bs[rr][cc] = B[(size_t)rr * HC + col0 + cc];
    }
    __syncthreads();
    int tx = tid & 15, ty = tid >> 4;
    ull acc2[4][2] = {};
#pragma unroll 16
    for (int k = 0; k < 64; ++k) {
        ull b01 = *reinterpret_cast<const ull*>(&Bs[k][tx * 4]);
        ull b23 = *reinterpret_cast<const ull*>(&Bs[k][tx * 4 + 2]);
#pragma unroll
        for (int m = 0; m < 4; ++m) {
            ull am2 = pack2s(As[ty * 4 + m][k]);
            acc2[m][0] = fma2(am2, b01, acc2[m][0]);
            acc2[m][1] = fma2(am2, b23, acc2[m][1]);
        }
    }
#pragma unroll
    for (int m = 0; m < 4; ++m) {
        int gr = row0 + ty * 4 + m;
        float2 lo = ull2f(acc2[m][0]);
        float2 hi = ull2f(acc2[m][1]);
        int gc = col0 + tx * 4;
        float4 bv = *reinterpret_cast<const float4*>(bias + gc);
        *reinterpret_cast<float4*>(C + (size_t)gr * HC + gc) =
            make_float4(lo.x + bv.x, lo.y + bv.y, hi.x + bv.z, hi.y + bv.w);
    }
}

// ----------------- fused LSTM step: gate-striped GEMM + in-register pointwise --------------
#define LSTMF_SMEM ((64 * 66 + 64 * 258) * 4)
__global__ __launch_bounds__(256) void lstm_fused_kernel(
    const float* __restrict__ xg, const float* __restrict__ WhhT,
    float* __restrict__ lh, float* __restrict__ lc, float* __restrict__ feats,
    int t, int first) {
    extern __shared__ float sm[];
    float* As = sm;            // [64][66]
    float* Bs = sm + 64 * 66;  // [64][258]
    int tid = threadIdx.x;
    int row0 = blockIdx.x * 64;
    int tx = tid & 15, ty = tid >> 4;
    ull acc[4][8] = {};
    if (!first) {
#pragma unroll
        for (int i = 0; i < 16; ++i) {
            int idx = tid + i * 256;
            int rr = idx >> 6, cc = idx & 63;
            int gn = row0 + rr;
            As[rr * 66 + cc] = (gn < NN) ? lh[(size_t)gn * 64 + cc] : 0.f;
        }
#pragma unroll
        for (int i = 0; i < 64; ++i) {
            int idx = tid + i * 256;
            int k = idx >> 8, g = idx & 255;
            Bs[k * 258 + g] = WhhT[idx];
        }
        __syncthreads();
#pragma unroll 8
        for (int k = 0; k < 64; ++k) {
            ull b[8];
#pragma unroll
            for (int g = 0; g < 4; ++g) {
                b[g * 2] = *reinterpret_cast<const ull*>(&Bs[k * 258 + g * 64 + tx * 4]);
                b[g * 2 + 1] = *reinterpret_cast<const ull*>(&Bs[k * 258 + g * 64 + tx * 4 + 2]);
            }
#pragma unroll
            for (int m = 0; m < 4; ++m) {
                ull a2 = pack2s(As[(ty * 4 + m) * 66 + k]);
#pragma unroll
                for (int j = 0; j < 8; ++j) acc[m][j] = fma2(a2, b[j], acc[m][j]);
            }
        }
    }
#pragma unroll
    for (int m = 0; m < 4; ++m) {
        int gn = row0 + ty * 4 + m;
        if (gn >= NN) continue;
        float gv[4][4];
#pragma unroll
        for (int g = 0; g < 4; ++g) {
            float2 lo = ull2f(acc[m][g * 2]);
            float2 hi = ull2f(acc[m][g * 2 + 1]);
            float4 xv = *reinterpret_cast<const float4*>(
                xg + ((size_t)t * NN + gn) * HC + g * 64 + tx * 4);
            gv[g][0] = lo.x + xv.x; gv[g][1] = lo.y + xv.y;
            gv[g][2] = hi.x + xv.z; gv[g][3] = hi.y + xv.w;
        }
        float cp[4] = {0.f, 0.f, 0.f, 0.f};
        if (!first) {
            float4 cprev = *reinterpret_cast<const float4*>(lc + (size_t)gn * 64 + tx * 4);
            cp[0] = cprev.x; cp[1] = cprev.y; cp[2] = cprev.z; cp[3] = cprev.w;
        }
        float cn[4], hn[4];
#pragma unroll
        for (int o = 0; o < 4; ++o) {
            float ci = sigmoidf_(gv[1][o]) * cp[o] + sigmoidf_(gv[0][o]) * tanhf(gv[2][o]);
            cn[o] = ci;
            hn[o] = sigmoidf_(gv[3][o]) * tanhf(ci);
        }
        *reinterpret_cast<float4*>(lc + (size_t)gn * 64 + tx * 4) =
            make_float4(cn[0], cn[1], cn[2], cn[3]);
        *reinterpret_cast<float4*>(lh + (size_t)gn * 64 + tx * 4) =
            make_float4(hn[0], hn[1], hn[2], hn[3]);
        *reinterpret_cast<float4*>(feats + ((size_t)gn * TT + t) * 64 + tx * 4) =
            make_float4(hn[0], hn[1], hn[2], hn[3]);
    }
}

// ----------------- relation scores: 4 rows per warp iteration -----------------
__global__ __launch_bounds__(256) void relation_kernel(
    const float* __restrict__ hmat, const float* __restrict__ W1,
    const float* __restrict__ b1, const float* __restrict__ W2,
    float* __restrict__ ssum) {
    extern __shared__ float sm[];
    float2* sW1v = reinterpret_cast<float2*>(sm);  // 8192 float2
    float* sb1 = sm + 16384;
    float* sW2 = sm + 16640;
    float* sbins = sm + 16896;
    int tid = threadIdx.x;
    for (int i = tid; i < 8192; i += 256) {
        int k = i >> 7;
        int rem = i & 127;
        int p = rem >> 5, l = rem & 31;
        int j1 = k * 256 + p * 64 + l;
        sW1v[i] = make_float2(W1[j1], W1[j1 + 32]);
    }
    if (tid < 256) { sb1[tid] = b1[tid]; sW2[tid] = W2[tid]; }
    if (tid < TT * RR) sbins[tid] = 0.f;
    __syncthreads();
    int lane = tid & 31;
    int gw = (blockIdx.x * blockDim.x + tid) >> 5;
    int nwarps = (gridDim.x * blockDim.x) >> 5;
    const int groups = (TT * NN * RR) / 4;  // 40000
    const int NR = NN * RR;
    const ull* wbase = reinterpret_cast<const ull*>(sW1v) + lane;
    for (int g = gw; g < groups; g += nwarps) {
        int row = g * 4;
        const float* hr = hmat + (size_t)row * CC;
        float h0[4], h1[4];
#pragma unroll
        for (int j = 0; j < 4; ++j) {
            h0[j] = hr[j * 64 + lane];
            h1[j] = hr[j * 64 + lane + 32];
        }
        ull a2[4][4] = {};
#pragma unroll 4
        for (int k = 0; k < 32; ++k) {
            const ull* w = wbase + k * 128;
            ull w0 = w[0], w1 = w[32], w2 = w[64], w3 = w[96];
#pragma unroll
            for (int j = 0; j < 4; ++j) {
                ull hk2 = pack2s(__shfl_sync(0xffffffffu, h0[j], k));
                a2[j][0] = fma2(hk2, w0, a2[j][0]);
                a2[j][1] = fma2(hk2, w1, a2[j][1]);
                a2[j][2] = fma2(hk2, w2, a2[j][2]);
                a2[j][3] = fma2(hk2, w3, a2[j][3]);
            }
        }
#pragma unroll 4
        for (int k = 0; k < 32; ++k) {
            const ull* w = wbase + (k + 32) * 128;
            ull w0 = w[0], w1 = w[32], w2 = w[64], w3 = w[96];
#pragma unroll
            for (int j = 0; j < 4; ++j) {
                ull hk2 = pack2s(__shfl_sync(0xffffffffu, h1[j], k));
                a2[j][0] = fma2(hk2, w0, a2[j][0]);
                a2[j][1] = fma2(hk2, w1, a2[j][1]);
                a2[j][2] = fma2(hk2, w2, a2[j][2]);
                a2[j][3] = fma2(hk2, w3, a2[j][3]);
            }
        }
        float acc[4];
#pragma unroll
        for (int j = 0; j < 4; ++j) {
            float s = 0.f;
#pragma unroll
            for (int p = 0; p < 4; ++p) {
                float2 av = ull2f(a2[j][p]);
                int j1 = p * 64 + lane, j2 = j1 + 32;
                s += tanh_approx(av.x + sb1[j1]) * sW2[j1];
                s += tanh_approx(av.y + sb1[j2]) * sW2[j2];
            }
            acc[j] = s;
        }
        float accA = acc[0] + acc[2];
        float accB = acc[1] + acc[3];
#pragma unroll
        for (int off2 = 16; off2 > 0; off2 >>= 1) {
            accA += __shfl_down_sync(0xffffffffu, accA, off2);
            accB += __shfl_down_sync(0xffffffffu, accB, off2);
        }
        if (lane == 0) {
            int binb = (row / NR) * RR;
            atomicAdd(&sbins[binb], accA);
            atomicAdd(&sbins[binb + 1], accB);
        }
    }
    __syncthreads();
    if (tid < TT * RR) atomicAdd(&ssum[tid], sbins[tid]);
}

__global__ void beta_kernel(const float* __restrict__ ssum, float* __restrict__ beta) {
    int t = threadIdx.x;
    if (t < TT) {
        float s0 = ssum[t * RR + 0] * (1.0f / NN);
        float s1 = ssum[t * RR + 1] * (1.0f / NN);
        float m = fmaxf(s0, s1);
        float e0 = expf(s0 - m), e1 = expf(s1 - m);
        float inv = 1.f / (e0 + e1);
        beta[t * RR + 0] = e0 * inv;
        beta[t * RR + 1] = e1 * inv;
    }
}

// ----------------- temporal multi-head attention: warp handles 2 nodes -----------------
__global__ __launch_bounds__(256) void attn_kernel(
    const float* __restrict__ feats, const float* __restrict__ pos,
    const float* __restrict__ Wq, const float* __restrict__ Wk, const float* __restrict__ Wv,
    float* __restrict__ out) {
    extern __shared__ float sm[];
    float* sWq = sm;
    float* sWk = sm + 4096;
    float* sWv = sm + 8192;
    float* spos = sm + 12288;
    float* wb = sm + 12544;
    int tid = threadIdx.x;
    for (int i = tid; i < 4096; i += 256) {
        sWq[i] = Wq[i]; sWk[i] = Wk[i]; sWv[i] = Wv[i];
    }
    if (tid < 256) spos[tid] = pos[tid];
    __syncthreads();
    int wid = tid >> 5, lane = tid & 31;
    int nbase = blockIdx.x * 8 + wid;
    float* ti = wb + wid * 1088;
    float* q = ti + 256;
    float* k_ = q + 256;
    float* v = k_ + 256;
    float* a = v + 256;
#pragma unroll
    for (int rep = 0; rep < 2; ++rep) {
        int n = nbase + rep * (NN / 2);
#pragma unroll
        for (int m = 0; m < 8; ++m) {
            int o = m * 32 + lane;
            ti[o] = feats[(size_t)n * 256 + o] + spos[o];
        }
        __syncwarp();
        {
            const ull* wq64 = reinterpret_cast<const ull*>(sWq);
            const ull* wk64 = reinterpret_cast<const ull*>(sWk);
            const ull* wv64 = reinterpret_cast<const ull*>(sWv);
            ull q2[4] = {}, k2[4] = {}, v2[4] = {};
#pragma unroll 4
            for (int k = 0; k < 64; ++k) {
                ull wq = wq64[k * 32 + lane];
                ull wk = wk64[k * 32 + lane];
                ull wv = wv64[k * 32 + lane];
#pragma unroll
                for (int t = 0; t < 4; ++t) {
                    ull tv = pack2s(ti[t * 64 + k]);
                    q2[t] = fma2(tv, wq, q2[t]);
                    k2[t] = fma2(tv, wk, k2[t]);
                    v2[t] = fma2(tv, wv, v2[t]);
                }
            }
#pragma unroll
            for (int t = 0; t < 4; ++t) {
                reinterpret_cast<float2*>(q)[t * 32 + lane] = ull2f(q2[t]);
                reinterpret_cast<float2*>(k_)[t * 32 + lane] = ull2f(k2[t]);
                reinterpret_cast<float2*>(v)[t * 32 + lane] = ull2f(v2[t]);
            }
        }
        __syncwarp();
        if (lane < 16) {
            int h = lane >> 2, tq = lane & 3;
            float sc[4];
            for (int tk = 0; tk <= tq; ++tk) {
                float s = 0.f;
#pragma unroll
                for (int ch = 0; ch < 16; ++ch)
                    s += q[tq * 64 + h * 16 + ch] * k_[tk * 64 + h * 16 + ch];
                sc[tk] = s * 0.5f;
            }
            float mx = sc[0];
            for (int tk = 1; tk <= tq; ++tk) mx = fmaxf(mx, sc[tk]);
            float sum = 0.f;
            for (int tk = 0; tk <= tq; ++tk) { sc[tk] = __expf(sc[tk] - mx); sum += sc[tk]; }
            float inv = 1.f / sum;
            for (int tk = 0; tk < 4; ++tk)
                a[h * 16 + tq * 4 + tk] = (tk <= tq) ? sc[tk] * inv : 0.f;
        }
        __syncwarp();
        {
            int h = lane >> 3;
            const ull* v64 = reinterpret_cast<const ull*>(v);
#pragma unroll
            for (int tq = 0; tq < 4; ++tq) {
                ull acc = 0ull;
#pragma unroll
                for (int tk = 0; tk < 4; ++tk)
                    acc = fma2(pack2s(a[h * 16 + tq * 4 + tk]), v64[tk * 32 + lane], acc);
                reinterpret_cast<float2*>(out + (size_t)n * 256 + tq * 64)[lane] = ull2f(acc);
            }
        }
        __syncwarp();
    }
}

// ----------------- host launch -----------------
template <typename T>
static T* symaddr(const void* sym) {
    void* p = nullptr;
    cudaGetSymbolAddress(&p, sym);
    return (T*)p;
}

extern "C" void kernel_launch(void* const* d_in, const int* in_sizes, int n_in,
                              void* d_out, int out_size) {
    const float* x = (const float*)d_in[0];
    const int* ei = (const int*)d_in[1];
    const float* W_src = (const float*)d_in[2];
    const float* W_dst = (const float*)d_in[3];
    const float* att_src = (const float*)d_in[4];
    const float* att_dst = (const float*)d_in[5];
    const float* ra_W1 = (const float*)d_in[6];
    const float* ra_b1 = (const float*)d_in[7];
    const float* ra_W2 = (const float*)d_in[8];
    const float* Wih = (const float*)d_in[9];
    const float* Whh = (const float*)d_in[10];
    const float* bih = (const float*)d_in[11];
    const float* bhh = (const float*)d_in[12];
    const float* pos = (const float*)d_in[13];
    const float* Wq = (const float*)d_in[14];
    const float* Wk = (const float*)d_in[15];
    const float* Wv = (const float*)d_in[16];
    float* out = (float*)d_out;

    float* agg = symaddr<float>(g_agg);
    float* als = symaddr<float>(g_als);
    float* ald = symaddr<float>(g_ald);
    float* intra = symaddr<float>(g_intra);
    float* ssum = symaddr<float>(g_ssum);
    float* beta = symaddr<float>(g_beta);
    float* xg = symaddr<float>(g_xg);
    float* lh = symaddr<float>(g_lh);
    float* lc = symaddr<float>(g_lc);
    float* feats = symaddr<float>(g_feats);
    float* WihT = symaddr<float>(g_WihT);
    float* WhhT = symaddr<float>(g_WhhT);
    float* biassum = symaddr<float>(g_biassum);
    float* folds = symaddr<float>(g_folds);
    float* foldd = symaddr<float>(g_foldd);
    float* Bstack = symaddr<float>(g_Bstack);
    int* cnt = symaddr<int>(g_cnt);
    int* off = symaddr<int>(g_off);
    int* posb = symaddr<int>(g_pos);
    int* sorted = symaddr<int>(g_sorted);
    ull* wsort8 = symaddr<ull>(g_wsort8);

    const int REL_SMEM = (16384 + 256 + 256 + 8) * 4;
    const int ATT_SMEM = (12544 + 8 * 1088) * 4;
    cudaFuncSetAttribute(relation_kernel, cudaFuncAttributeMaxDynamicSharedMemorySize, REL_SMEM);
    cudaFuncSetAttribute(attn_kernel, cudaFuncAttributeMaxDynamicSharedMemorySize, ATT_SMEM);
    cudaFuncSetAttribute(gemm_intra128, cudaFuncAttributeMaxDynamicSharedMemorySize, GI_SMEM);
    cudaFuncSetAttribute(lstm_fused_kernel, cudaFuncAttributeMaxDynamicSharedMemorySize,
                         LSTMF_SMEM);

    // ---- prep (cnt zeroing fused in) + CSR/GAT front
    prep_kernel<<<PREP_BLOCKS, 256>>>(W_src, W_dst, att_src, att_dst, Wih, Whh, bih, bhh,
                                      folds, foldd, Bstack, WihT, WhhT, biassum, cnt);
    alshist_kernel<<<ALS_BLOCKS + HIST_BLOCKS, 256>>>(x, folds, foldd, ei, als, ald, cnt);
    scan_kernel<<<ZZ, 1024>>>(cnt, off, posb);
    scatter_kernel<<<(ZZ * EE) / 256, 256>>>(ei, als, ald, posb, sorted, wsort8);
    gather_kernel<<<dim3(NN / 8, ZZ), 256>>>(off, sorted, wsort8, x, agg);

    // ---- batched intra GEMM (128-row tiles)
    gemm_intra128<<<dim3((NN + 127) / 128, ZZ), 256, GI_SMEM>>>(agg, Bstack, intra);

    // ---- relation aggregation
    cudaMemsetAsync(ssum, 0, TT * RR * sizeof(float), 0);
    relation_kernel<<<444, 256, REL_SMEM>>>(intra, ra_W1, ra_b1, ra_W2, ssum);
    beta_kernel<<<1, 32>>>(ssum, beta);

    // ---- LSTM: beta-fused xg GEMM, then per-step fused kernels (t=0 specialized)
    gemm_xg<<<dim3(HC / 64, (TT * NN) / 64), 256>>>(intra, beta, WihT, biassum, xg);
    for (int t = 0; t < TT; ++t) {
        lstm_fused_kernel<<<(NN + 63) / 64, 256, LSTMF_SMEM>>>(xg, WhhT, lh, lc, feats, t,
                                                               t == 0 ? 1 : 0);
    }

    // ---- temporal attention
    attn_kernel<<<(NN + 15) / 16, 256, ATT_SMEM>>>(feats, pos, Wq, Wk, Wv, out);
}

// round 13
// speedup vs baseline: 1.0402x; 1.0082x over previous
#include <cuda_runtime.h>
#include <cuda_fp16.h>
#include <math.h>
#include <stdint.h>

#define TT 4
#define NN 20000
#define EE 320000
#define RR 2
#define DD 64
#define HH 4
#define CC 64
#define HC 256   // H*C
#define ZZ 8     // T*R

typedef unsigned long long ull;

// ----------------- scratch (static device globals; no allocation) -----------------
__device__ __align__(16) float g_agg[ZZ * NN * HC];
__device__ __align__(16) float g_als[ZZ * NN * HH];
__device__ __align__(16) float g_ald[ZZ * NN * HH];
__device__ __align__(16) float g_intra[TT * NN * RR * CC];
__device__ float g_ssum[TT * RR];
__device__ float g_beta[TT * RR];
__device__ __align__(16) float g_xg[TT * NN * HC];
__device__ __align__(16) float g_lh[NN * CC];
__device__ __align__(16) float g_lc[NN * CC];
__device__ __align__(16) float g_feats[NN * TT * CC];
__device__ float g_WihT[DD * HC];
__device__ float g_WhhT[DD * HC];
__device__ float g_biassum[HC];
__device__ __align__(16) float g_folds[RR * DD * HH];
__device__ __align__(16) float g_foldd[RR * DD * HH];
__device__ float g_Bstack[RR * HC * CC];
__device__ int g_cnt[ZZ * NN];
__device__ int g_off[ZZ * (NN + 1)];
__device__ int g_rank[ZZ * EE];          // per-edge rank within its dst (dense, from hist)
__device__ int g_sorted[ZZ * EE];        // dense 4B/edge src stream (gather critical path)
__device__ __align__(8) ull g_wsort8[ZZ * EE];  // half4 weights, 8B/edge

// ----------------- helpers -----------------
__device__ __forceinline__ float sigmoidf_(float x) { return 1.0f / (1.0f + __expf(-x)); }

__device__ __forceinline__ float tanh_approx(float x) {
    float y; asm("tanh.approx.f32 %0, %1;" : "=f"(y) : "f"(x)); return y;
}
__device__ __forceinline__ ull fma2(ull a, ull b, ull c) {
    ull d;
    asm("fma.rn.f32x2 %0, %1, %2, %3;" : "=l"(d) : "l"(a), "l"(b), "l"(c));
    return d;
}
__device__ __forceinline__ ull pack2s(float x) {
    ull u; asm("mov.b64 %0, {%1,%1};" : "=l"(u) : "f"(x)); return u;
}
__device__ __forceinline__ ull pack2f(float x, float y) {
    ull u; asm("mov.b64 %0, {%1,%2};" : "=l"(u) : "f"(x), "f"(y)); return u;
}
__device__ __forceinline__ float2 ull2f(ull u) {
    float2 v; asm("mov.b64 {%0,%1}, %2;" : "=f"(v.x), "=f"(v.y) : "l"(u)); return v;
}
__device__ __forceinline__ float2 h2f2(unsigned int bits) {
    __half2 h = *reinterpret_cast<__half2*>(&bits);
    return __half22float2(h);
}

// ================= prep mega-kernel: fold + bstack + transposes + bias + cnt-zero ==========
#define PREP_BLOCKS (259 + 625)
__global__ __launch_bounds__(256) void prep_kernel(
    const float* __restrict__ Wsrc, const float* __restrict__ Wdst,
    const float* __restrict__ as_, const float* __restrict__ ad_,
    const float* __restrict__ Wih, const float* __restrict__ Whh,
    const float* __restrict__ bih, const float* __restrict__ bhh,
    float* __restrict__ fs, float* __restrict__ fd, float* __restrict__ Bst,
    float* __restrict__ WihT, float* __restrict__ WhhT, float* __restrict__ biassum,
    int* __restrict__ cnt) {
    int b = blockIdx.x, tid = threadIdx.x;
    if (b >= 259) {
        cnt[(b - 259) * 256 + tid] = 0;
        return;
    }
    if (b < 2) {
        int idx = b * 256 + tid;
        if (idx < RR * DD * HH) {
            int r = idx / (DD * HH);
            int k = (idx / HH) % DD;
            int h = idx % HH;
            float accs = 0.f, accd = 0.f;
            for (int c = 0; c < CC; ++c) {
                accs += Wsrc[((size_t)(r * DD + k)) * HC + h * CC + c] * as_[(r * HH + h) * CC + c];
                accd += Wdst[((size_t)(r * DD + k)) * HC + h * CC + c] * ad_[(r * HH + h) * CC + c];
            }
            fs[idx] = accs;
            fd[idx] = accd;
        }
    } else if (b < 130) {
        int idx = (b - 2) * 256 + tid;
        int r = idx / (HC * CC);
        int kk = (idx / CC) % HC;
        int co = idx % CC;
        int h = kk >> 6, ci = kk & 63;
        Bst[idx] = Wsrc[((size_t)(r * DD + ci)) * HC + h * 64 + co] * 0.25f;
    } else if (b < 194) {
        int idx = (b - 130) * 256 + tid;
        int r = idx / DD, c = idx % DD;
        WihT[c * HC + r] = Wih[idx];
    } else if (b < 258) {
        int idx = (b - 194) * 256 + tid;
        int r = idx / DD, c = idx % DD;
        WhhT[c * HC + r] = Whh[idx];
    } else {
        if (tid < HC) biassum[tid] = bih[tid] + bhh[tid];
    }
}

// ================= als + hist combined; hist also records per-edge rank =================
#define ALS_BLOCKS 625
#define HIST_BLOCKS 10000
__global__ __launch_bounds__(256) void alshist_kernel(
    const float* __restrict__ x, const float* __restrict__ fs, const float* __restrict__ fd,
    const int* __restrict__ ei, float* __restrict__ als, float* __restrict__ ald,
    int* __restrict__ cnt, int* __restrict__ rank) {
    int tid = threadIdx.x;
    if (blockIdx.x >= ALS_BLOCKS) {
        int i = (blockIdx.x - ALS_BLOCKS) * 256 + tid;
        int z = i / EE, e = i - z * EE;
        int dst = __ldg(ei + (size_t)z * 2 * EE + EE + e);
        rank[i] = atomicAdd(cnt + z * NN + dst, 1);
        return;
    }
    int idx = blockIdx.x * 256 + tid;
    int z = idx / NN, n = idx - z * NN;
    int t = z >> 1, r = z & 1;
    const float4* xr4 = reinterpret_cast<const float4*>(x + ((size_t)t * NN + n) * DD);
    const float4* fs4 = reinterpret_cast<const float4*>(fs + r * DD * HH);
    const float4* fd4 = reinterpret_cast<const float4*>(fd + r * DD * HH);
    float4 a = {0.f, 0.f, 0.f, 0.f}, b = {0.f, 0.f, 0.f, 0.f};
#pragma unroll
    for (int kk = 0; kk < 16; ++kk) {
        float4 xq = __ldg(xr4 + kk);
        float xv[4] = {xq.x, xq.y, xq.z, xq.w};
#pragma unroll
        for (int j = 0; j < 4; ++j) {
            int k = kk * 4 + j;
            float4 f = __ldg(fs4 + k);
            float4 g = __ldg(fd4 + k);
            a.x += xv[j] * f.x; a.y += xv[j] * f.y; a.z += xv[j] * f.z; a.w += xv[j] * f.w;
            b.x += xv[j] * g.x; b.y += xv[j] * g.y; b.z += xv[j] * g.z; b.w += xv[j] * g.w;
        }
    }
    reinterpret_cast<float4*>(als)[idx] = a;
    reinterpret_cast<float4*>(ald)[idx] = b;
}

// ----------------- CSR scan (off only) -----------------
__global__ __launch_bounds__(1024) void scan_kernel(const int* __restrict__ cnt,
                                                    int* __restrict__ off) {
    __shared__ int ssums[1024];
    int z = blockIdx.x;
    const int* c = cnt + z * NN;
    int* o = off + z * (NN + 1);
    int tid = threadIdx.x;
    const int CH = (NN + 1023) / 1024;  // 20
    int base = tid * CH;
    int s = 0;
    for (int i = 0; i < CH; ++i) {
        int idx = base + i;
        if (idx < NN) s += c[idx];
    }
    ssums[tid] = s;
    __syncthreads();
    for (int d = 1; d < 1024; d <<= 1) {
        int v = (tid >= d) ? ssums[tid - d] : 0;
        __syncthreads();
        ssums[tid] += v;
        __syncthreads();
    }
    int run = (tid > 0) ? ssums[tid - 1] : 0;
    for (int i = 0; i < CH; ++i) {
        int idx = base + i;
        if (idx < NN) {
            o[idx] = run;
            run += c[idx];
        }
    }
    if (tid == 1023) o[NN] = ssums[1023];
}

// scatter: NO atomic — position = off[dst] + precomputed rank
__global__ void scatter_kernel(const int* __restrict__ ei, const float* __restrict__ als,
                               const float* __restrict__ ald, const int* __restrict__ off,
                               const int* __restrict__ rank, int* __restrict__ sorted,
                               ull* __restrict__ wsort8) {
    int i = blockIdx.x * blockDim.x + threadIdx.x;
    if (i >= ZZ * EE) return;
    int z = i / EE, e = i - z * EE;
    int src = __ldg(ei + (size_t)z * 2 * EE + e);
    int dst = __ldg(ei + (size_t)z * 2 * EE + EE + e);
    float4 s4 = __ldg(reinterpret_cast<const float4*>(als) + (size_t)z * NN + src);
    float4 d4 = __ldg(reinterpret_cast<const float4*>(ald) + (size_t)z * NN + dst);
    float e0 = s4.x + d4.x; e0 = (e0 >= 0.f) ? e0 : 0.2f * e0;
    float e1 = s4.y + d4.y; e1 = (e1 >= 0.f) ? e1 : 0.2f * e1;
    float e2 = s4.z + d4.z; e2 = (e2 >= 0.f) ? e2 : 0.2f * e2;
    float e3 = s4.w + d4.w; e3 = (e3 >= 0.f) ? e3 : 0.2f * e3;
    __half2 h01 = __floats2half2_rn(__expf(e0), __expf(e1));
    __half2 h23 = __floats2half2_rn(__expf(e2), __expf(e3));
    unsigned int u01 = *reinterpret_cast<unsigned int*>(&h01);
    unsigned int u23 = *reinterpret_cast<unsigned int*>(&h23);
    ull w8 = (ull)u01 | ((ull)u23 << 32);
    int p = __ldg(off + z * (NN + 1) + dst) + __ldg(rank + i);
    sorted[(size_t)z * EE + p] = src;
    wsort8[(size_t)z * EE + p] = w8;
}

// ----------------- gather: warp per (z,dst); unroll x4; dense src + 8B weights -------------
__global__ __launch_bounds__(256) void gather_kernel(
    const int* __restrict__ off, const int* __restrict__ sorted,
    const ull* __restrict__ wsort8, const float* __restrict__ x,
    float* __restrict__ agg) {
    int z = blockIdx.y;
    int d = blockIdx.x * 8 + (threadIdx.x >> 5);
    int lane = threadIdx.x & 31;
    const float* xt = x + (size_t)(z >> 1) * NN * DD;
    const int* offz = off + z * (NN + 1);
    const int* sz = sorted + (size_t)z * EE;
    const ull* wz = wsort8 + (size_t)z * EE;
    int i = offz[d], iend = offz[d + 1];
    ull A0 = 0ull, A1 = 0ull, A2 = 0ull, A3 = 0ull;
    ull D01 = 0ull, D23 = 0ull;
    const ull ONES = pack2s(1.0f);
    while (i + 4 <= iend) {
        int s0 = __ldg(sz + i);
        int s1 = __ldg(sz + i + 1);
        int s2 = __ldg(sz + i + 2);
        int s3 = __ldg(sz + i + 3);
        ull w0 = __ldg(wz + i);
        ull w1 = __ldg(wz + i + 1);
        ull w2 = __ldg(wz + i + 2);
        ull w3 = __ldg(wz + i + 3);
        ull x0 = __ldg(reinterpret_cast<const ull*>(xt + (size_t)s0 * DD) + lane);
        ull x1 = __ldg(reinterpret_cast<const ull*>(xt + (size_t)s1 * DD) + lane);
        ull x2 = __ldg(reinterpret_cast<const ull*>(xt + (size_t)s2 * DD) + lane);
        ull x3 = __ldg(reinterpret_cast<const ull*>(xt + (size_t)s3 * DD) + lane);
        i += 4;
        float2 a01 = h2f2((unsigned int)w0), a23 = h2f2((unsigned int)(w0 >> 32));
        float2 b01 = h2f2((unsigned int)w1), b23 = h2f2((unsigned int)(w1 >> 32));
        float2 c01 = h2f2((unsigned int)w2), c23 = h2f2((unsigned int)(w2 >> 32));
        float2 d01v = h2f2((unsigned int)w3), d23v = h2f2((unsigned int)(w3 >> 32));
        D01 = fma2(pack2f(a01.x, a01.y), ONES, D01);
        D23 = fma2(pack2f(a23.x, a23.y), ONES, D23);
        A0 = fma2(pack2s(a01.x), x0, A0);
        A1 = fma2(pack2s(a01.y), x0, A1);
        A2 = fma2(pack2s(a23.x), x0, A2);
        A3 = fma2(pack2s(a23.y), x0, A3);
        D01 = fma2(pack2f(b01.x, b01.y), ONES, D01);
        D23 = fma2(pack2f(b23.x, b23.y), ONES, D23);
        A0 = fma2(pack2s(b01.x), x1, A0);
        A1 = fma2(pack2s(b01.y), x1, A1);
        A2 = fma2(pack2s(b23.x), x1, A2);
        A3 = fma2(pack2s(b23.y), x1, A3);
        D01 = fma2(pack2f(c01.x, c01.y), ONES, D01);
        D23 = fma2(pack2f(c23.x, c23.y), ONES, D23);
        A0 = fma2(pack2s(c01.x), x2, A0);
        A1 = fma2(pack2s(c01.y), x2, A1);
        A2 = fma2(pack2s(c23.x), x2, A2);
        A3 = fma2(pack2s(c23.y), x2, A3);
        D01 = fma2(pack2f(d01v.x, d01v.y), ONES, D01);
        D23 = fma2(pack2f(d23v.x, d23v.y), ONES, D23);
        A0 = fma2(pack2s(d01v.x), x3, A0);
        A1 = fma2(pack2s(d01v.y), x3, A1);
        A2 = fma2(pack2s(d23v.x), x3, A2);
        A3 = fma2(pack2s(d23v.y), x3, A3);
    }
    while (i < iend) {
        int s0 = __ldg(sz + i);
        ull w0 = __ldg(wz + i);
        ull x0 = __ldg(reinterpret_cast<const ull*>(xt + (size_t)s0 * DD) + lane);
        ++i;
        float2 a01 = h2f2((unsigned int)w0), a23 = h2f2((unsigned int)(w0 >> 32));
        D01 = fma2(pack2f(a01.x, a01.y), ONES, D01);
        D23 = fma2(pack2f(a23.x, a23.y), ONES, D23);
        A0 = fma2(pack2s(a01.x), x0, A0);
        A1 = fma2(pack2s(a01.y), x0, A1);
        A2 = fma2(pack2s(a23.x), x0, A2);
        A3 = fma2(pack2s(a23.y), x0, A3);
    }
    float2 d01 = ull2f(D01), d23 = ull2f(D23);
    float i0 = 1.f / (d01.x + 1e-16f), i1 = 1.f / (d01.y + 1e-16f);
    float i2 = 1.f / (d23.x + 1e-16f), i3 = 1.f / (d23.y + 1e-16f);
    float2 a0 = ull2f(A0), a1 = ull2f(A1), a2 = ull2f(A2), a3 = ull2f(A3);
    float2* o = reinterpret_cast<float2*>(agg + ((size_t)z * NN + d) * HC) + lane;
    o[0]  = make_float2(a0.x * i0, a0.y * i0);
    o[32] = make_float2(a1.x * i1, a1.y * i1);
    o[64] = make_float2(a2.x * i2, a2.y * i2);
    o[96] = make_float2(a3.x * i3, a3.y * i3);
}

// ----------------- batched intra GEMM: 128x64 tile, 8x4/thread, k-transposed A -------------
#define GI_SMEM ((64 * 130 + 64 * 66) * 4)
__global__ __launch_bounds__(256) void gemm_intra128(const float* __restrict__ Abase,
                                                     const float* __restrict__ Bbase,
                                                     float* __restrict__ Cbase) {
    extern __shared__ float sm[];
    float* Ast = sm;            // [64 k][130]
    float* Bs = sm + 64 * 130;  // [64 k][66]
    int z = blockIdx.y;
    int tq = z >> 1, r = z & 1;
    const float* A = Abase + (size_t)z * NN * HC;
    const float* B = Bbase + (size_t)r * HC * CC;
    float* C = Cbase + (size_t)tq * NN * RR * CC + r * CC;
    int tid = threadIdx.x;
    int row0 = blockIdx.x * 128;
    int tx = tid & 15, ty = tid >> 4;
    ull acc[8][2] = {};
    for (int kc = 0; kc < HC; kc += 64) {
#pragma unroll
        for (int i = 0; i < 32; ++i) {
            int idx = tid + i * 256;
            int rr = idx >> 6, cc = idx & 63;
            int gr = row0 + rr;
            Ast[cc * 130 + rr] = (gr < NN) ? A[(size_t)gr * HC + kc + cc] : 0.f;
        }
#pragma unroll
        for (int i = 0; i < 16; ++i) {
            int idx = tid + i * 256;
            int rr = idx >> 6, cc = idx & 63;
            Bs[rr * 66 + cc] = B[(size_t)(kc + rr) * CC + cc];
        }
        __syncthreads();
#pragma unroll 8
        for (int k = 0; k < 64; ++k) {
            ull b01 = *reinterpret_cast<const ull*>(&Bs[k * 66 + tx * 4]);
            ull b23 = *reinterpret_cast<const ull*>(&Bs[k * 66 + tx * 4 + 2]);
            const float* ar = &Ast[k * 130 + ty * 8];
            float2 f01 = ull2f(*reinterpret_cast<const ull*>(ar));
            float2 f23 = ull2f(*reinterpret_cast<const ull*>(ar + 2));
            float2 f45 = ull2f(*reinterpret_cast<const ull*>(ar + 4));
            float2 f67 = ull2f(*reinterpret_cast<const ull*>(ar + 6));
            float av[8] = {f01.x, f01.y, f23.x, f23.y, f45.x, f45.y, f67.x, f67.y};
#pragma unroll
            for (int m = 0; m < 8; ++m) {
                ull am = pack2s(av[m]);
                acc[m][0] = fma2(am, b01, acc[m][0]);
                acc[m][1] = fma2(am, b23, acc[m][1]);
            }
        }
        __syncthreads();
    }
#pragma unroll
    for (int m = 0; m < 8; ++m) {
        int gr = row0 + ty * 8 + m;
        if (gr < NN) {
            float2 lo = ull2f(acc[m][0]), hi = ull2f(acc[m][1]);
            *reinterpret_cast<float4*>(C + (size_t)gr * (RR * CC) + tx * 4) =
                make_float4(lo.x, lo.y, hi.x, hi.y);
        }
    }
}

// ----------------- xg GEMM: A = beta-combined intra, K=64 -----------------
__global__ __launch_bounds__(256) void gemm_xg(
    const float* __restrict__ intra, const float* __restrict__ beta,
    const float* __restrict__ B, const float* __restrict__ bias, float* __restrict__ C) {
    __shared__ float As[64][66];
    __shared__ float Bs[64][66];
    int tid = threadIdx.x;
    int row0 = blockIdx.y * 64;
    int col0 = blockIdx.x * 64;
#pragma unroll
    for (int i = 0; i < 16; ++i) {
        int idx = tid + i * 256;
        int rr = idx >> 6, cc = idx & 63;
        int gr = row0 + rr;
        int t = gr / NN;
        size_t base = (size_t)gr * (RR * CC) + cc;
        As[rr][cc] = __ldg(beta + t * 2) * __ldg(intra + base) +
                     __ldg(beta + t * 2 + 1) * __ldg(intra + base + CC);
        Bs[rr][cc] = B[(size_t)rr * HC + col0 + cc];
    }
    __syncthreads();
    int tx = tid & 15, ty = tid >> 4;
    ull acc2[4][2] = {};
#pragma unroll 16
    for (int k = 0; k < 64; ++k) {
        ull b01 = *reinterpret_cast<const ull*>(&Bs[k][tx * 4]);
        ull b23 = *reinterpret_cast<const ull*>(&Bs[k][tx * 4 + 2]);
#pragma unroll
        for (int m = 0; m < 4; ++m) {
            ull am2 = pack2s(As[ty * 4 + m][k]);
            acc2[m][0] = fma2(am2, b01, acc2[m][0]);
            acc2[m][1] = fma2(am2, b23, acc2[m][1]);
        }
    }
#pragma unroll
    for (int m = 0; m < 4; ++m) {
        int gr = row0 + ty * 4 + m;
        float2 lo = ull2f(acc2[m][0]);
        float2 hi = ull2f(acc2[m][1]);
        int gc = col0 + tx * 4;
        float4 bv = *reinterpret_cast<const float4*>(bias + gc);
        *reinterpret_cast<float4*>(C + (size_t)gr * HC + gc) =
            make_float4(lo.x + bv.x, lo.y + bv.y, hi.x + bv.z, hi.y + bv.w);
    }
}

// ----------------- fused LSTM step: gate-striped GEMM + in-register pointwise --------------
#define LSTMF_SMEM ((64 * 66 + 64 * 258) * 4)
__global__ __launch_bounds__(256) void lstm_fused_kernel(
    const float* __restrict__ xg, const float* __restrict__ WhhT,
    float* __restrict__ lh, float* __restrict__ lc, float* __restrict__ feats,
    int t, int first) {
    extern __shared__ float sm[];
    float* As = sm;            // [64][66]
    float* Bs = sm + 64 * 66;  // [64][258]
    int tid = threadIdx.x;
    int row0 = blockIdx.x * 64;
    int tx = tid & 15, ty = tid >> 4;
    ull acc[4][8] = {};
    if (!first) {
#pragma unroll
        for (int i = 0; i < 16; ++i) {
            int idx = tid + i * 256;
            int rr = idx >> 6, cc = idx & 63;
            int gn = row0 + rr;
            As[rr * 66 + cc] = (gn < NN) ? lh[(size_t)gn * 64 + cc] : 0.f;
        }
#pragma unroll
        for (int i = 0; i < 64; ++i) {
            int idx = tid + i * 256;
            int k = idx >> 8, g = idx & 255;
            Bs[k * 258 + g] = WhhT[idx];
        }
        __syncthreads();
#pragma unroll 8
        for (int k = 0; k < 64; ++k) {
            ull b[8];
#pragma unroll
            for (int g = 0; g < 4; ++g) {
                b[g * 2] = *reinterpret_cast<const ull*>(&Bs[k * 258 + g * 64 + tx * 4]);
                b[g * 2 + 1] = *reinterpret_cast<const ull*>(&Bs[k * 258 + g * 64 + tx * 4 + 2]);
            }
#pragma unroll
            for (int m = 0; m < 4; ++m) {
                ull a2 = pack2s(As[(ty * 4 + m) * 66 + k]);
#pragma unroll
                for (int j = 0; j < 8; ++j) acc[m][j] = fma2(a2, b[j], acc[m][j]);
            }
        }
    }
#pragma unroll
    for (int m = 0; m < 4; ++m) {
        int gn = row0 + ty * 4 + m;
        if (gn >= NN) continue;
        float gv[4][4];
#pragma unroll
        for (int g = 0; g < 4; ++g) {
            float2 lo = ull2f(acc[m][g * 2]);
            float2 hi = ull2f(acc[m][g * 2 + 1]);
            float4 xv = *reinterpret_cast<const float4*>(
                xg + ((size_t)t * NN + gn) * HC + g * 64 + tx * 4);
            gv[g][0] = lo.x + xv.x; gv[g][1] = lo.y + xv.y;
            gv[g][2] = hi.x + xv.z; gv[g][3] = hi.y + xv.w;
        }
        float cp[4] = {0.f, 0.f, 0.f, 0.f};
        if (!first) {
            float4 cprev = *reinterpret_cast<const float4*>(lc + (size_t)gn * 64 + tx * 4);
            cp[0] = cprev.x; cp[1] = cprev.y; cp[2] = cprev.z; cp[3] = cprev.w;
        }
        float cn[4], hn[4];
#pragma unroll
        for (int o = 0; o < 4; ++o) {
            float ci = sigmoidf_(gv[1][o]) * cp[o] + sigmoidf_(gv[0][o]) * tanhf(gv[2][o]);
            cn[o] = ci;
            hn[o] = sigmoidf_(gv[3][o]) * tanhf(ci);
        }
        *reinterpret_cast<float4*>(lc + (size_t)gn * 64 + tx * 4) =
            make_float4(cn[0], cn[1], cn[2], cn[3]);
        *reinterpret_cast<float4*>(lh + (size_t)gn * 64 + tx * 4) =
            make_float4(hn[0], hn[1], hn[2], hn[3]);
        *reinterpret_cast<float4*>(feats + ((size_t)gn * TT + t) * 64 + tx * 4) =
            make_float4(hn[0], hn[1], hn[2], hn[3]);
    }
}

// ----------------- relation scores: 4 rows per warp iteration -----------------
__global__ __launch_bounds__(256) void relation_kernel(
    const float* __restrict__ hmat, const float* __restrict__ W1,
    const float* __restrict__ b1, const float* __restrict__ W2,
    float* __restrict__ ssum) {
    extern __shared__ float sm[];
    float2* sW1v = reinterpret_cast<float2*>(sm);  // 8192 float2
    float* sb1 = sm + 16384;
    float* sW2 = sm + 16640;
    float* sbins = sm + 16896;
    int tid = threadIdx.x;
    for (int i = tid; i < 8192; i += 256) {
        int k = i >> 7;
        int rem = i & 127;
        int p = rem >> 5, l = rem & 31;
        int j1 = k * 256 + p * 64 + l;
        sW1v[i] = make_float2(W1[j1], W1[j1 + 32]);
    }
    if (tid < 256) { sb1[tid] = b1[tid]; sW2[tid] = W2[tid]; }
    if (tid < TT * RR) sbins[tid] = 0.f;
    __syncthreads();
    int lane = tid & 31;
    int gw = (blockIdx.x * blockDim.x + tid) >> 5;
    int nwarps = (gridDim.x * blockDim.x) >> 5;
    const int groups = (TT * NN * RR) / 4;  // 40000
    const int NR = NN * RR;
    const ull* wbase = reinterpret_cast<const ull*>(sW1v) + lane;
    for (int g = gw; g < groups; g += nwarps) {
        int row = g * 4;
        const float* hr = hmat + (size_t)row * CC;
        float h0[4], h1[4];
#pragma unroll
        for (int j = 0; j < 4; ++j) {
            h0[j] = hr[j * 64 + lane];
            h1[j] = hr[j * 64 + lane + 32];
        }
        ull a2[4][4] = {};
#pragma unroll 4
        for (int k = 0; k < 32; ++k) {
            const ull* w = wbase + k * 128;
            ull w0 = w[0], w1 = w[32], w2 = w[64], w3 = w[96];
#pragma unroll
            for (int j = 0; j < 4; ++j) {
                ull hk2 = pack2s(__shfl_sync(0xffffffffu, h0[j], k));
                a2[j][0] = fma2(hk2, w0, a2[j][0]);
                a2[j][1] = fma2(hk2, w1, a2[j][1]);
                a2[j][2] = fma2(hk2, w2, a2[j][2]);
                a2[j][3] = fma2(hk2, w3, a2[j][3]);
            }
        }
#pragma unroll 4
        for (int k = 0; k < 32; ++k) {
            const ull* w = wbase + (k + 32) * 128;
            ull w0 = w[0], w1 = w[32], w2 = w[64], w3 = w[96];
#pragma unroll
            for (int j = 0; j < 4; ++j) {
                ull hk2 = pack2s(__shfl_sync(0xffffffffu, h1[j], k));
                a2[j][0] = fma2(hk2, w0, a2[j][0]);
                a2[j][1] = fma2(hk2, w1, a2[j][1]);
                a2[j][2] = fma2(hk2, w2, a2[j][2]);
                a2[j][3] = fma2(hk2, w3, a2[j][3]);
            }
        }
        float acc[4];
#pragma unroll
        for (int j = 0; j < 4; ++j) {
            float s = 0.f;
#pragma unroll
            for (int p = 0; p < 4; ++p) {
                float2 av = ull2f(a2[j][p]);
                int j1 = p * 64 + lane, j2 = j1 + 32;
                s += tanh_approx(av.x + sb1[j1]) * sW2[j1];
                s += tanh_approx(av.y + sb1[j2]) * sW2[j2];
            }
            acc[j] = s;
        }
        float accA = acc[0] + acc[2];
        float accB = acc[1] + acc[3];
#pragma unroll
        for (int off2 = 16; off2 > 0; off2 >>= 1) {
            accA += __shfl_down_sync(0xffffffffu, accA, off2);
            accB += __shfl_down_sync(0xffffffffu, accB, off2);
        }
        if (lane == 0) {
            int binb = (row / NR) * RR;
            atomicAdd(&sbins[binb], accA);
            atomicAdd(&sbins[binb + 1], accB);
        }
    }
    __syncthreads();
    if (tid < TT * RR) atomicAdd(&ssum[tid], sbins[tid]);
}

__global__ void beta_kernel(const float* __restrict__ ssum, float* __restrict__ beta) {
    int t = threadIdx.x;
    if (t < TT) {
        float s0 = ssum[t * RR + 0] * (1.0f / NN);
        float s1 = ssum[t * RR + 1] * (1.0f / NN);
        float m = fmaxf(s0, s1);
        float e0 = expf(s0 - m), e1 = expf(s1 - m);
        float inv = 1.f / (e0 + e1);
        beta[t * RR + 0] = e0 * inv;
        beta[t * RR + 1] = e1 * inv;
    }
}

// ----------------- temporal multi-head attention: warp handles 4 nodes -----------------
__global__ __launch_bounds__(256) void attn_kernel(
    const float* __restrict__ feats, const float* __restrict__ pos,
    const float* __restrict__ Wq, const float* __restrict__ Wk, const float* __restrict__ Wv,
    float* __restrict__ out) {
    extern __shared__ float sm[];
    float* sWq = sm;
    float* sWk = sm + 4096;
    float* sWv = sm + 8192;
    float* spos = sm + 12288;
    float* wb = sm + 12544;
    int tid = threadIdx.x;
    for (int i = tid; i < 4096; i += 256) {
        sWq[i] = Wq[i]; sWk[i] = Wk[i]; sWv[i] = Wv[i];
    }
    if (tid < 256) spos[tid] = pos[tid];
    __syncthreads();
    int wid = tid >> 5, lane = tid & 31;
    int nbase = blockIdx.x * 8 + wid;
    float* ti = wb + wid * 1088;
    float* q = ti + 256;
    float* k_ = q + 256;
    float* v = k_ + 256;
    float* a = v + 256;
#pragma unroll
    for (int rep = 0; rep < 4; ++rep) {
        int n = nbase + rep * (NN / 4);
#pragma unroll
        for (int m = 0; m < 8; ++m) {
            int o = m * 32 + lane;
            ti[o] = feats[(size_t)n * 256 + o] + spos[o];
        }
        __syncwarp();
        {
            const ull* wq64 = reinterpret_cast<const ull*>(sWq);
            const ull* wk64 = reinterpret_cast<const ull*>(sWk);
            const ull* wv64 = reinterpret_cast<const ull*>(sWv);
            ull q2[4] = {}, k2[4] = {}, v2[4] = {};
#pragma unroll 4
            for (int k = 0; k < 64; ++k) {
                ull wq = wq64[k * 32 + lane];
                ull wk = wk64[k * 32 + lane];
                ull wv = wv64[k * 32 + lane];
#pragma unroll
                for (int t = 0; t < 4; ++t) {
                    ull tv = pack2s(ti[t * 64 + k]);
                    q2[t] = fma2(tv, wq, q2[t]);
                    k2[t] = fma2(tv, wk, k2[t]);
                    v2[t] = fma2(tv, wv, v2[t]);
                }
            }
#pragma unroll
            for (int t = 0; t < 4; ++t) {
                reinterpret_cast<float2*>(q)[t * 32 + lane] = ull2f(q2[t]);
                reinterpret_cast<float2*>(k_)[t * 32 + lane] = ull2f(k2[t]);
                reinterpret_cast<float2*>(v)[t * 32 + lane] = ull2f(v2[t]);
            }
        }
        __syncwarp();
        if (lane < 16) {
            int h = lane >> 2, tq = lane & 3;
            float sc[4];
            for (int tk = 0; tk <= tq; ++tk) {
                float s = 0.f;
#pragma unroll
                for (int ch = 0; ch < 16; ++ch)
                    s += q[tq * 64 + h * 16 + ch] * k_[tk * 64 + h * 16 + ch];
                sc[tk] = s * 0.5f;
            }
            float mx = sc[0];
            for (int tk = 1; tk <= tq; ++tk) mx = fmaxf(mx, sc[tk]);
            float sum = 0.f;
            for (int tk = 0; tk <= tq; ++tk) { sc[tk] = __expf(sc[tk] - mx); sum += sc[tk]; }
            float inv = 1.f / sum;
            for (int tk = 0; tk < 4; ++tk)
                a[h * 16 + tq * 4 + tk] = (tk <= tq) ? sc[tk] * inv : 0.f;
        }
        __syncwarp();
        {
            int h = lane >> 3;
            const ull* v64 = reinterpret_cast<const ull*>(v);
#pragma unroll
            for (int tq = 0; tq < 4; ++tq) {
                ull acc = 0ull;
#pragma unroll
                for (int tk = 0; tk < 4; ++tk)
                    acc = fma2(pack2s(a[h * 16 + tq * 4 + tk]), v64[tk * 32 + lane], acc);
                reinterpret_cast<float2*>(out + (size_t)n * 256 + tq * 64)[lane] = ull2f(acc);
            }
        }
        __syncwarp();
    }
}

// ----------------- host launch -----------------
template <typename T>
static T* symaddr(const void* sym) {
    void* p = nullptr;
    cudaGetSymbolAddress(&p, sym);
    return (T*)p;
}

extern "C" void kernel_launch(void* const* d_in, const int* in_sizes, int n_in,
                              void* d_out, int out_size) {
    const float* x = (const float*)d_in[0];
    const int* ei = (const int*)d_in[1];
    const float* W_src = (const float*)d_in[2];
    const float* W_dst = (const float*)d_in[3];
    const float* att_src = (const float*)d_in[4];
    const float* att_dst = (const float*)d_in[5];
    const float* ra_W1 = (const float*)d_in[6];
    const float* ra_b1 = (const float*)d_in[7];
    const float* ra_W2 = (const float*)d_in[8];
    const float* Wih = (const float*)d_in[9];
    const float* Whh = (const float*)d_in[10];
    const float* bih = (const float*)d_in[11];
    const float* bhh = (const float*)d_in[12];
    const float* pos = (const float*)d_in[13];
    const float* Wq = (const float*)d_in[14];
    const float* Wk = (const float*)d_in[15];
    const float* Wv = (const float*)d_in[16];
    float* out = (float*)d_out;

    float* agg = symaddr<float>(g_agg);
    float* als = symaddr<float>(g_als);
    float* ald = symaddr<float>(g_ald);
    float* intra = symaddr<float>(g_intra);
    float* ssum = symaddr<float>(g_ssum);
    float* beta = symaddr<float>(g_beta);
    float* xg = symaddr<float>(g_xg);
    float* lh = symaddr<float>(g_lh);
    float* lc = symaddr<float>(g_lc);
    float* feats = symaddr<float>(g_feats);
    float* WihT = symaddr<float>(g_WihT);
    float* WhhT = symaddr<float>(g_WhhT);
    float* biassum = symaddr<float>(g_biassum);
    float* folds = symaddr<float>(g_folds);
    float* foldd = symaddr<float>(g_foldd);
    float* Bstack = symaddr<float>(g_Bstack);
    int* cnt = symaddr<int>(g_cnt);
    int* off = symaddr<int>(g_off);
    int* rank = symaddr<int>(g_rank);
    int* sorted = symaddr<int>(g_sorted);
    ull* wsort8 = symaddr<ull>(g_wsort8);

    const int REL_SMEM = (16384 + 256 + 256 + 8) * 4;
    const int ATT_SMEM = (12544 + 8 * 1088) * 4;
    cudaFuncSetAttribute(relation_kernel, cudaFuncAttributeMaxDynamicSharedMemorySize, REL_SMEM);
    cudaFuncSetAttribute(attn_kernel, cudaFuncAttributeMaxDynamicSharedMemorySize, ATT_SMEM);
    cudaFuncSetAttribute(gemm_intra128, cudaFuncAttributeMaxDynamicSharedMemorySize, GI_SMEM);
    cudaFuncSetAttribute(lstm_fused_kernel, cudaFuncAttributeMaxDynamicSharedMemorySize,
                         LSTMF_SMEM);

    // ---- prep (cnt zeroing fused in) + CSR/GAT front (atomic-free scatter)
    prep_kernel<<<PREP_BLOCKS, 256>>>(W_src, W_dst, att_src, att_dst, Wih, Whh, bih, bhh,
                                      folds, foldd, Bstack, WihT, WhhT, biassum, cnt);
    alshist_kernel<<<ALS_BLOCKS + HIST_BLOCKS, 256>>>(x, folds, foldd, ei, als, ald, cnt, rank);
    scan_kernel<<<ZZ, 1024>>>(cnt, off);
    scatter_kernel<<<(ZZ * EE) / 256, 256>>>(ei, als, ald, off, rank, sorted, wsort8);
    gather_kernel<<<dim3(NN / 8, ZZ), 256>>>(off, sorted, wsort8, x, agg);

    // ---- batched intra GEMM (128-row tiles)
    gemm_intra128<<<dim3((NN + 127) / 128, ZZ), 256, GI_SMEM>>>(agg, Bstack, intra);

    // ---- relation aggregation
    cudaMemsetAsync(ssum, 0, TT * RR * sizeof(float), 0);
    relation_kernel<<<444, 256, REL_SMEM>>>(intra, ra_W1, ra_b1, ra_W2, ssum);
    beta_kernel<<<1, 32>>>(ssum, beta);

    // ---- LSTM: beta-fused xg GEMM, then per-step fused kernels (t=0 specialized)
    gemm_xg<<<dim3(HC / 64, (TT * NN) / 64), 256>>>(intra, beta, WihT, biassum, xg);
    for (int t = 0; t < TT; ++t) {
        lstm_fused_kernel<<<(NN + 63) / 64, 256, LSTMF_SMEM>>>(xg, WhhT, lh, lc, feats, t,
                                                               t == 0 ? 1 : 0);
    }

    // ---- temporal attention (4 nodes per warp)
    attn_kernel<<<(NN + 31) / 32, 256, ATT_SMEM>>>(feats, pos, Wq, Wk, Wv, out);
}

// round 15
// speedup vs baseline: 1.0402x; 1.0001x over previous
#include <cuda_runtime.h>
#include <cuda_fp16.h>
#include <math.h>
#include <stdint.h>

#define TT 4
#define NN 20000
#define EE 320000
#define RR 2
#define DD 64
#define HH 4
#define CC 64
#define HC 256   // H*C
#define ZZ 8     // T*R

typedef unsigned long long ull;

// ----------------- scratch (static device globals; no allocation) -----------------
__device__ __align__(16) float g_agg[ZZ * NN * HC];
__device__ __align__(16) float g_als[ZZ * NN * HH];
__device__ __align__(16) float g_ald[ZZ * NN * HH];
__device__ __align__(16) float g_intra[TT * NN * RR * CC];
__device__ float g_ssum[TT * RR];
__device__ float g_beta[TT * RR];
__device__ __align__(16) float g_xg[TT * NN * HC];
__device__ __align__(16) float g_lh[NN * CC];
__device__ __align__(16) float g_lc[NN * CC];
__device__ __align__(16) float g_feats[NN * TT * CC];
__device__ float g_WihT[DD * HC];
__device__ float g_WhhT[DD * HC];
__device__ float g_biassum[HC];
__device__ __align__(16) float g_folds[RR * DD * HH];
__device__ __align__(16) float g_foldd[RR * DD * HH];
__device__ float g_Bstack[RR * HC * CC];
__device__ int g_cnt[ZZ * NN];
__device__ int g_off[ZZ * (NN + 1)];
__device__ __align__(8) int g_rank[ZZ * EE];
__device__ int g_sorted[ZZ * EE];        // dense 4B/edge src stream (gather critical path)
__device__ __align__(8) ull g_wsort8[ZZ * EE];  // half4 weights, 8B/edge

// ----------------- helpers -----------------
__device__ __forceinline__ float sigmoidf_(float x) { return 1.0f / (1.0f + __expf(-x)); }

__device__ __forceinline__ float tanh_approx(float x) {
    float y; asm("tanh.approx.f32 %0, %1;" : "=f"(y) : "f"(x)); return y;
}
__device__ __forceinline__ ull fma2(ull a, ull b, ull c) {
    ull d;
    asm("fma.rn.f32x2 %0, %1, %2, %3;" : "=l"(d) : "l"(a), "l"(b), "l"(c));
    return d;
}
__device__ __forceinline__ ull pack2s(float x) {
    ull u; asm("mov.b64 %0, {%1,%1};" : "=l"(u) : "f"(x)); return u;
}
__device__ __forceinline__ ull pack2f(float x, float y) {
    ull u; asm("mov.b64 %0, {%1,%2};" : "=l"(u) : "f"(x), "f"(y)); return u;
}
__device__ __forceinline__ float2 ull2f(ull u) {
    float2 v; asm("mov.b64 {%0,%1}, %2;" : "=f"(v.x), "=f"(v.y) : "l"(u)); return v;
}
__device__ __forceinline__ float2 h2f2(unsigned int bits) {
    __half2 h = *reinterpret_cast<__half2*>(&bits);
    return __half22float2(h);
}

// ================= prep mega-kernel: fold + bstack + transposes + bias + cnt-zero ==========
#define PREP_BLOCKS (259 + 625)
__global__ __launch_bounds__(256) void prep_kernel(
    const float* __restrict__ Wsrc, const float* __restrict__ Wdst,
    const float* __restrict__ as_, const float* __restrict__ ad_,
    const float* __restrict__ Wih, const float* __restrict__ Whh,
    const float* __restrict__ bih, const float* __restrict__ bhh,
    float* __restrict__ fs, float* __restrict__ fd, float* __restrict__ Bst,
    float* __restrict__ WihT, float* __restrict__ WhhT, float* __restrict__ biassum,
    int* __restrict__ cnt) {
    int b = blockIdx.x, tid = threadIdx.x;
    if (b >= 259) {
        cnt[(b - 259) * 256 + tid] = 0;
        return;
    }
    if (b < 2) {
        int idx = b * 256 + tid;
        if (idx < RR * DD * HH) {
            int r = idx / (DD * HH);
            int k = (idx / HH) % DD;
            int h = idx % HH;
            float accs = 0.f, accd = 0.f;
            for (int c = 0; c < CC; ++c) {
                accs += Wsrc[((size_t)(r * DD + k)) * HC + h * CC + c] * as_[(r * HH + h) * CC + c];
                accd += Wdst[((size_t)(r * DD + k)) * HC + h * CC + c] * ad_[(r * HH + h) * CC + c];
            }
            fs[idx] = accs;
            fd[idx] = accd;
        }
    } else if (b < 130) {
        int idx = (b - 2) * 256 + tid;
        int r = idx / (HC * CC);
        int kk = (idx / CC) % HC;
        int co = idx % CC;
        int h = kk >> 6, ci = kk & 63;
        Bst[idx] = Wsrc[((size_t)(r * DD + ci)) * HC + h * 64 + co] * 0.25f;
    } else if (b < 194) {
        int idx = (b - 130) * 256 + tid;
        int r = idx / DD, c = idx % DD;
        WihT[c * HC + r] = Wih[idx];
    } else if (b < 258) {
        int idx = (b - 194) * 256 + tid;
        int r = idx / DD, c = idx % DD;
        WhhT[c * HC + r] = Whh[idx];
    } else {
        if (tid < HC) biassum[tid] = bih[tid] + bhh[tid];
    }
}

// ================= als + hist combined; hist also records per-edge rank =================
#define ALS_BLOCKS 625
#define HIST_BLOCKS 10000
__global__ __launch_bounds__(256) void alshist_kernel(
    const float* __restrict__ x, const float* __restrict__ fs, const float* __restrict__ fd,
    const int* __restrict__ ei, float* __restrict__ als, float* __restrict__ ald,
    int* __restrict__ cnt, int* __restrict__ rank) {
    int tid = threadIdx.x;
    if (blockIdx.x >= ALS_BLOCKS) {
        int i = (blockIdx.x - ALS_BLOCKS) * 256 + tid;
        int z = i / EE, e = i - z * EE;
        int dst = __ldg(ei + (size_t)z * 2 * EE + EE + e);
        rank[i] = atomicAdd(cnt + z * NN + dst, 1);
        return;
    }
    int idx = blockIdx.x * 256 + tid;
    int z = idx / NN, n = idx - z * NN;
    int t = z >> 1, r = z & 1;
    const float4* xr4 = reinterpret_cast<const float4*>(x + ((size_t)t * NN + n) * DD);
    const float4* fs4 = reinterpret_cast<const float4*>(fs + r * DD * HH);
    const float4* fd4 = reinterpret_cast<const float4*>(fd + r * DD * HH);
    float4 a = {0.f, 0.f, 0.f, 0.f}, b = {0.f, 0.f, 0.f, 0.f};
#pragma unroll
    for (int kk = 0; kk < 16; ++kk) {
        float4 xq = __ldg(xr4 + kk);
        float xv[4] = {xq.x, xq.y, xq.z, xq.w};
#pragma unroll
        for (int j = 0; j < 4; ++j) {
            int k = kk * 4 + j;
            float4 f = __ldg(fs4 + k);
            float4 g = __ldg(fd4 + k);
            a.x += xv[j] * f.x; a.y += xv[j] * f.y; a.z += xv[j] * f.z; a.w += xv[j] * f.w;
            b.x += xv[j] * g.x; b.y += xv[j] * g.y; b.z += xv[j] * g.z; b.w += xv[j] * g.w;
        }
    }
    reinterpret_cast<float4*>(als)[idx] = a;
    reinterpret_cast<float4*>(ald)[idx] = b;
}

// ----------------- CSR scan (off only) -----------------
__global__ __launch_bounds__(1024) void scan_kernel(const int* __restrict__ cnt,
                                                    int* __restrict__ off) {
    __shared__ int ssums[1024];
    int z = blockIdx.x;
    const int* c = cnt + z * NN;
    int* o = off + z * (NN + 1);
    int tid = threadIdx.x;
    const int CH = (NN + 1023) / 1024;  // 20
    int base = tid * CH;
    int s = 0;
    for (int i = 0; i < CH; ++i) {
        int idx = base + i;
        if (idx < NN) s += c[idx];
    }
    ssums[tid] = s;
    __syncthreads();
    for (int d = 1; d < 1024; d <<= 1) {
        int v = (tid >= d) ? ssums[tid - d] : 0;
        __syncthreads();
        ssums[tid] += v;
        __syncthreads();
    }
    int run = (tid > 0) ? ssums[tid - 1] : 0;
    for (int i = 0; i < CH; ++i) {
        int idx = base + i;
        if (idx < NN) {
            o[idx] = run;
            run += c[idx];
        }
    }
    if (tid == 1023) o[NN] = ssums[1023];
}

// scatter: NO atomic; 2 edges/thread; int2 vectorized dense loads
__global__ void scatter_kernel(const int* __restrict__ ei, const float* __restrict__ als,
                               const float* __restrict__ ald, const int* __restrict__ off,
                               const int* __restrict__ rank, int* __restrict__ sorted,
                               ull* __restrict__ wsort8) {
    int pair = blockIdx.x * blockDim.x + threadIdx.x;  // handles edges 2*pair, 2*pair+1
    if (pair >= (ZZ * EE) / 2) return;
    int i = pair * 2;
    int z = i / EE, e = i - z * EE;  // EE even -> both edges in same z
    const int* eiz = ei + (size_t)z * 2 * EE;
    int2 src2 = __ldg(reinterpret_cast<const int2*>(eiz + e));
    int2 dst2 = __ldg(reinterpret_cast<const int2*>(eiz + EE + e));
    int2 rk2 = __ldg(reinterpret_cast<const int2*>(rank + i));
    const float4* alsz = reinterpret_cast<const float4*>(als) + (size_t)z * NN;
    const float4* aldz = reinterpret_cast<const float4*>(ald) + (size_t)z * NN;
    const int* offz = off + z * (NN + 1);
#pragma unroll
    for (int j = 0; j < 2; ++j) {
        int src = (j == 0) ? src2.x : src2.y;
        int dst = (j == 0) ? dst2.x : dst2.y;
        int rk = (j == 0) ? rk2.x : rk2.y;
        float4 s4 = __ldg(alsz + src);
        float4 d4 = __ldg(aldz + dst);
        float e0 = s4.x + d4.x; e0 = (e0 >= 0.f) ? e0 : 0.2f * e0;
        float e1 = s4.y + d4.y; e1 = (e1 >= 0.f) ? e1 : 0.2f * e1;
        float e2 = s4.z + d4.z; e2 = (e2 >= 0.f) ? e2 : 0.2f * e2;
        float e3 = s4.w + d4.w; e3 = (e3 >= 0.f) ? e3 : 0.2f * e3;
        __half2 h01 = __floats2half2_rn(__expf(e0), __expf(e1));
        __half2 h23 = __floats2half2_rn(__expf(e2), __expf(e3));
        unsigned int u01 = *reinterpret_cast<unsigned int*>(&h01);
        unsigned int u23 = *reinterpret_cast<unsigned int*>(&h23);
        ull w8 = (ull)u01 | ((ull)u23 << 32);
        int p = __ldg(offz + dst) + rk;
        sorted[(size_t)z * EE + p] = src;
        wsort8[(size_t)z * EE + p] = w8;
    }
}

// ----------------- gather: warp per (z,dst); unroll x4; dense src + 8B weights -------------
__global__ __launch_bounds__(256) void gather_kernel(
    const int* __restrict__ off, const int* __restrict__ sorted,
    const ull* __restrict__ wsort8, const float* __restrict__ x,
    float* __restrict__ agg) {
    int z = blockIdx.y;
    int d = blockIdx.x * 8 + (threadIdx.x >> 5);
    int lane = threadIdx.x & 31;
    const float* xt = x + (size_t)(z >> 1) * NN * DD;
    const int* offz = off + z * (NN + 1);
    const int* sz = sorted + (size_t)z * EE;
    const ull* wz = wsort8 + (size_t)z * EE;
    int i = offz[d], iend = offz[d + 1];
    ull A0 = 0ull, A1 = 0ull, A2 = 0ull, A3 = 0ull;
    ull D01 = 0ull, D23 = 0ull;
    const ull ONES = pack2s(1.0f);
    while (i + 4 <= iend) {
        int s0 = __ldg(sz + i);
        int s1 = __ldg(sz + i + 1);
        int s2 = __ldg(sz + i + 2);
        int s3 = __ldg(sz + i + 3);
        ull w0 = __ldg(wz + i);
        ull w1 = __ldg(wz + i + 1);
        ull w2 = __ldg(wz + i + 2);
        ull w3 = __ldg(wz + i + 3);
        ull x0 = __ldg(reinterpret_cast<const ull*>(xt + (size_t)s0 * DD) + lane);
        ull x1 = __ldg(reinterpret_cast<const ull*>(xt + (size_t)s1 * DD) + lane);
        ull x2 = __ldg(reinterpret_cast<const ull*>(xt + (size_t)s2 * DD) + lane);
        ull x3 = __ldg(reinterpret_cast<const ull*>(xt + (size_t)s3 * DD) + lane);
        i += 4;
        float2 a01 = h2f2((unsigned int)w0), a23 = h2f2((unsigned int)(w0 >> 32));
        float2 b01 = h2f2((unsigned int)w1), b23 = h2f2((unsigned int)(w1 >> 32));
        float2 c01 = h2f2((unsigned int)w2), c23 = h2f2((unsigned int)(w2 >> 32));
        float2 d01v = h2f2((unsigned int)w3), d23v = h2f2((unsigned int)(w3 >> 32));
        D01 = fma2(pack2f(a01.x, a01.y), ONES, D01);
        D23 = fma2(pack2f(a23.x, a23.y), ONES, D23);
        A0 = fma2(pack2s(a01.x), x0, A0);
        A1 = fma2(pack2s(a01.y), x0, A1);
        A2 = fma2(pack2s(a23.x), x0, A2);
        A3 = fma2(pack2s(a23.y), x0, A3);
        D01 = fma2(pack2f(b01.x, b01.y), ONES, D01);
        D23 = fma2(pack2f(b23.x, b23.y), ONES, D23);
        A0 = fma2(pack2s(b01.x), x1, A0);
        A1 = fma2(pack2s(b01.y), x1, A1);
        A2 = fma2(pack2s(b23.x), x1, A2);
        A3 = fma2(pack2s(b23.y), x1, A3);
        D01 = fma2(pack2f(c01.x, c01.y), ONES, D01);
        D23 = fma2(pack2f(c23.x, c23.y), ONES, D23);
        A0 = fma2(pack2s(c01.x), x2, A0);
        A1 = fma2(pack2s(c01.y), x2, A1);
        A2 = fma2(pack2s(c23.x), x2, A2);
        A3 = fma2(pack2s(c23.y), x2, A3);
        D01 = fma2(pack2f(d01v.x, d01v.y), ONES, D01);
        D23 = fma2(pack2f(d23v.x, d23v.y), ONES, D23);
        A0 = fma2(pack2s(d01v.x), x3, A0);
        A1 = fma2(pack2s(d01v.y), x3, A1);
        A2 = fma2(pack2s(d23v.x), x3, A2);
        A3 = fma2(pack2s(d23v.y), x3, A3);
    }
    while (i < iend) {
        int s0 = __ldg(sz + i);
        ull w0 = __ldg(wz + i);
        ull x0 = __ldg(reinterpret_cast<const ull*>(xt + (size_t)s0 * DD) + lane);
        ++i;
        float2 a01 = h2f2((unsigned int)w0), a23 = h2f2((unsigned int)(w0 >> 32));
        D01 = fma2(pack2f(a01.x, a01.y), ONES, D01);
        D23 = fma2(pack2f(a23.x, a23.y), ONES, D23);
        A0 = fma2(pack2s(a01.x), x0, A0);
        A1 = fma2(pack2s(a01.y), x0, A1);
        A2 = fma2(pack2s(a23.x), x0, A2);
        A3 = fma2(pack2s(a23.y), x0, A3);
    }
    float2 d01 = ull2f(D01), d23 = ull2f(D23);
    float i0 = 1.f / (d01.x + 1e-16f), i1 = 1.f / (d01.y + 1e-16f);
    float i2 = 1.f / (d23.x + 1e-16f), i3 = 1.f / (d23.y + 1e-16f);
    float2 a0 = ull2f(A0), a1 = ull2f(A1), a2 = ull2f(A2), a3 = ull2f(A3);
    float2* o = reinterpret_cast<float2*>(agg + ((size_t)z * NN + d) * HC) + lane;
    o[0]  = make_float2(a0.x * i0, a0.y * i0);
    o[32] = make_float2(a1.x * i1, a1.y * i1);
    o[64] = make_float2(a2.x * i2, a2.y * i2);
    o[96] = make_float2(a3.x * i3, a3.y * i3);
}

// ----------------- batched intra GEMM: 128x64 tile, 8x4/thread, k-transposed A -------------
#define GI_SMEM ((64 * 130 + 64 * 66) * 4)
__global__ __launch_bounds__(256) void gemm_intra128(const float* __restrict__ Abase,
                                                     const float* __restrict__ Bbase,
                                                     float* __restrict__ Cbase) {
    extern __shared__ float sm[];
    float* Ast = sm;            // [64 k][130]
    float* Bs = sm + 64 * 130;  // [64 k][66]
    int z = blockIdx.y;
    int tq = z >> 1, r = z & 1;
    const float* A = Abase + (size_t)z * NN * HC;
    const float* B = Bbase + (size_t)r * HC * CC;
    float* C = Cbase + (size_t)tq * NN * RR * CC + r * CC;
    int tid = threadIdx.x;
    int row0 = blockIdx.x * 128;
    int tx = tid & 15, ty = tid >> 4;
    ull acc[8][2] = {};
    for (int kc = 0; kc < HC; kc += 64) {
#pragma unroll
        for (int i = 0; i < 32; ++i) {
            int idx = tid + i * 256;
            int rr = idx >> 6, cc = idx & 63;
            int gr = row0 + rr;
            Ast[cc * 130 + rr] = (gr < NN) ? A[(size_t)gr * HC + kc + cc] : 0.f;
        }
#pragma unroll
        for (int i = 0; i < 16; ++i) {
            int idx = tid + i * 256;
            int rr = idx >> 6, cc = idx & 63;
            Bs[rr * 66 + cc] = B[(size_t)(kc + rr) * CC + cc];
        }
        __syncthreads();
#pragma unroll 8
        for (int k = 0; k < 64; ++k) {
            ull b01 = *reinterpret_cast<const ull*>(&Bs[k * 66 + tx * 4]);
            ull b23 = *reinterpret_cast<const ull*>(&Bs[k * 66 + tx * 4 + 2]);
            const float* ar = &Ast[k * 130 + ty * 8];
            float2 f01 = ull2f(*reinterpret_cast<const ull*>(ar));
            float2 f23 = ull2f(*reinterpret_cast<const ull*>(ar + 2));
            float2 f45 = ull2f(*reinterpret_cast<const ull*>(ar + 4));
            float2 f67 = ull2f(*reinterpret_cast<const ull*>(ar + 6));
            float av[8] = {f01.x, f01.y, f23.x, f23.y, f45.x, f45.y, f67.x, f67.y};
#pragma unroll
            for (int m = 0; m < 8; ++m) {
                ull am = pack2s(av[m]);
                acc[m][0] = fma2(am, b01, acc[m][0]);
                acc[m][1] = fma2(am, b23, acc[m][1]);
            }
        }
        __syncthreads();
    }
#pragma unroll
    for (int m = 0; m < 8; ++m) {
        int gr = row0 + ty * 8 + m;
        if (gr < NN) {
            float2 lo = ull2f(acc[m][0]), hi = ull2f(acc[m][1]);
            *reinterpret_cast<float4*>(C + (size_t)gr * (RR * CC) + tx * 4) =
                make_float4(lo.x, lo.y, hi.x, hi.y);
        }
    }
}

// ----------------- xg GEMM: A = beta-combined intra, K=64 -----------------
__global__ __launch_bounds__(256) void gemm_xg(
    const float* __restrict__ intra, const float* __restrict__ beta,
    const float* __restrict__ B, const float* __restrict__ bias, float* __restrict__ C) {
    __shared__ float As[64][66];
    __shared__ float Bs[64][66];
    int tid = threadIdx.x;
    int row0 = blockIdx.y * 64;
    int col0 = blockIdx.x * 64;
#pragma unroll
    for (int i = 0; i < 16; ++i) {
        int idx = tid + i * 256;
        int rr = idx >> 6, cc = idx & 63;
        int gr = row0 + rr;
        int t = gr / NN;
        size_t base = (size_t)gr * (RR * CC) + cc;
        As[rr][cc] = __ldg(beta + t * 2) * __ldg(intra + base) +
                     __ldg(beta + t * 2 + 1) * __ldg(intra + base + CC);
        Bs[rr][cc] = B[(size_t)rr * HC + col0 + cc];
    }
    __syncthreads();
    int tx = tid & 15, ty = tid >> 4;
    ull acc2[4][2] = {};
#pragma unroll 16
    for (int k = 0; k < 64; ++k) {
        ull b01 = *reinterpret_cast<const ull*>(&Bs[k][tx * 4]);
        ull b23 = *reinterpret_cast<const ull*>(&Bs[k][tx * 4 + 2]);
#pragma unroll
        for (int m = 0; m < 4; ++m) {
            ull am2 = pack2s(As[ty * 4 + m][k]);
            acc2[m][0] = fma2(am2, b01, acc2[m][0]);
            acc2[m][1] = fma2(am2, b23, acc2[m][1]);
        }
    }
#pragma unroll
    for (int m = 0; m < 4; ++m) {
        int gr = row0 + ty * 4 + m;
        float2 lo = ull2f(acc2[m][0]);
        float2 hi = ull2f(acc2[m][1]);
        int gc = col0 + tx * 4;
        float4 bv = *reinterpret_cast<const float4*>(bias + gc);
        *reinterpret_cast<float4*>(C + (size_t)gr * HC + gc) =
            make_float4(lo.x + bv.x, lo.y + bv.y, hi.x + bv.z, hi.y + bv.w);
    }
}

// ----------------- fused LSTM step: gate-striped GEMM + in-register pointwise --------------
#define LSTMF_SMEM ((64 * 66 + 64 * 258) * 4)
__global__ __launch_bounds__(256) void lstm_fused_kernel(
    const float* __restrict__ xg, const float* __restrict__ WhhT,
    float* __restrict__ lh, float* __restrict__ lc, float* __restrict__ feats,
    int t, int first) {
    extern __shared__ float sm[];
    float* As = sm;            // [64][66]
    float* Bs = sm + 64 * 66;  // [64][258]
    int tid = threadIdx.x;
    int row0 = blockIdx.x * 64;
    int tx = tid & 15, ty = tid >> 4;
    ull acc[4][8] = {};
    if (!first) {
#pragma unroll
        for (int i = 0; i < 16; ++i) {
            int idx = tid + i * 256;
            int rr = idx >> 6, cc = idx & 63;
            int gn = row0 + rr;
            As[rr * 66 + cc] = (gn < NN) ? lh[(size_t)gn * 64 + cc] : 0.f;
        }
#pragma unroll
        for (int i = 0; i < 64; ++i) {
            int idx = tid + i * 256;
            int k = idx >> 8, g = idx & 255;
            Bs[k * 258 + g] = WhhT[idx];
        }
        __syncthreads();
#pragma unroll 8
        for (int k = 0; k < 64; ++k) {
            ull b[8];
#pragma unroll
            for (int g = 0; g < 4; ++g) {
                b[g * 2] = *reinterpret_cast<const ull*>(&Bs[k * 258 + g * 64 + tx * 4]);
                b[g * 2 + 1] = *reinterpret_cast<const ull*>(&Bs[k * 258 + g * 64 + tx * 4 + 2]);
            }
#pragma unroll
            for (int m = 0; m < 4; ++m) {
                ull a2 = pack2s(As[(ty * 4 + m) * 66 + k]);
#pragma unroll
                for (int j = 0; j < 8; ++j) acc[m][j] = fma2(a2, b[j], acc[m][j]);
            }
        }
    }
#pragma unroll
    for (int m = 0; m < 4; ++m) {
        int gn = row0 + ty * 4 + m;
        if (gn >= NN) continue;
        float gv[4][4];
#pragma unroll
        for (int g = 0; g < 4; ++g) {
            float2 lo = ull2f(acc[m][g * 2]);
            float2 hi = ull2f(acc[m][g * 2 + 1]);
            float4 xv = *reinterpret_cast<const float4*>(
                xg + ((size_t)t * NN + gn) * HC + g * 64 + tx * 4);
            gv[g][0] = lo.x + xv.x; gv[g][1] = lo.y + xv.y;
            gv[g][2] = hi.x + xv.z; gv[g][3] = hi.y + xv.w;
        }
        float cp[4] = {0.f, 0.f, 0.f, 0.f};
        if (!first) {
            float4 cprev = *reinterpret_cast<const float4*>(lc + (size_t)gn * 64 + tx * 4);
            cp[0] = cprev.x; cp[1] = cprev.y; cp[2] = cprev.z; cp[3] = cprev.w;
        }
        float cn[4], hn[4];
#pragma unroll
        for (int o = 0; o < 4; ++o) {
            float ci = sigmoidf_(gv[1][o]) * cp[o] + sigmoidf_(gv[0][o]) * tanhf(gv[2][o]);
            cn[o] = ci;
            hn[o] = sigmoidf_(gv[3][o]) * tanhf(ci);
        }
        *reinterpret_cast<float4*>(lc + (size_t)gn * 64 + tx * 4) =
            make_float4(cn[0], cn[1], cn[2], cn[3]);
        *reinterpret_cast<float4*>(lh + (size_t)gn * 64 + tx * 4) =
            make_float4(hn[0], hn[1], hn[2], hn[3]);
        *reinterpret_cast<float4*>(feats + ((size_t)gn * TT + t) * 64 + tx * 4) =
            make_float4(hn[0], hn[1], hn[2], hn[3]);
    }
}

// ----------------- relation scores: 4 rows per warp iteration -----------------
__global__ __launch_bounds__(256) void relation_kernel(
    const float* __restrict__ hmat, const float* __restrict__ W1,
    const float* __restrict__ b1, const float* __restrict__ W2,
    float* __restrict__ ssum) {
    extern __shared__ float sm[];
    float2* sW1v = reinterpret_cast<float2*>(sm);  // 8192 float2
    float* sb1 = sm + 16384;
    float* sW2 = sm + 16640;
    float* sbins = sm + 16896;
    int tid = threadIdx.x;
    for (int i = tid; i < 8192; i += 256) {
        int k = i >> 7;
        int rem = i & 127;
        int p = rem >> 5, l = rem & 31;
        int j1 = k * 256 + p * 64 + l;
        sW1v[i] = make_float2(W1[j1], W1[j1 + 32]);
    }
    if (tid < 256) { sb1[tid] = b1[tid]; sW2[tid] = W2[tid]; }
    if (tid < TT * RR) sbins[tid] = 0.f;
    __syncthreads();
    int lane = tid & 31;
    int gw = (blockIdx.x * blockDim.x + tid) >> 5;
    int nwarps = (gridDim.x * blockDim.x) >> 5;
    const int groups = (TT * NN * RR) / 4;  // 40000
    const int NR = NN * RR;
    const ull* wbase = reinterpret_cast<const ull*>(sW1v) + lane;
    for (int g = gw; g < groups; g += nwarps) {
        int row = g * 4;
        const float* hr = hmat + (size_t)row * CC;
        float h0[4], h1[4];
#pragma unroll
        for (int j = 0; j < 4; ++j) {
            h0[j] = hr[j * 64 + lane];
            h1[j] = hr[j * 64 + lane + 32];
        }
        ull a2[4][4] = {};
#pragma unroll 4
        for (int k = 0; k < 32; ++k) {
            const ull* w = wbase + k * 128;
            ull w0 = w[0], w1 = w[32], w2 = w[64], w3 = w[96];
#pragma unroll
            for (int j = 0; j < 4; ++j) {
                ull hk2 = pack2s(__shfl_sync(0xffffffffu, h0[j], k));
                a2[j][0] = fma2(hk2, w0, a2[j][0]);
                a2[j][1] = fma2(hk2, w1, a2[j][1]);
                a2[j][2] = fma2(hk2, w2, a2[j][2]);
                a2[j][3] = fma2(hk2, w3, a2[j][3]);
            }
        }
#pragma unroll 4
        for (int k = 0; k < 32; ++k) {
            const ull* w = wbase + (k + 32) * 128;
            ull w0 = w[0], w1 = w[32], w2 = w[64], w3 = w[96];
#pragma unroll
            for (int j = 0; j < 4; ++j) {
                ull hk2 = pack2s(__shfl_sync(0xffffffffu, h1[j], k));
                a2[j][0] = fma2(hk2, w0, a2[j][0]);
                a2[j][1] = fma2(hk2, w1, a2[j][1]);
                a2[j][2] = fma2(hk2, w2, a2[j][2]);
                a2[j][3] = fma2(hk2, w3, a2[j][3]);
            }
        }
        float acc[4];
#pragma unroll
        for (int j = 0; j < 4; ++j) {
            float s = 0.f;
#pragma unroll
            for (int p = 0; p < 4; ++p) {
                float2 av = ull2f(a2[j][p]);
                int j1 = p * 64 + lane, j2 = j1 + 32;
                s += tanh_approx(av.x + sb1[j1]) * sW2[j1];
                s += tanh_approx(av.y + sb1[j2]) * sW2[j2];
            }
            acc[j] = s;
        }
        float accA = acc[0] + acc[2];
        float accB = acc[1] + acc[3];
#pragma unroll
        for (int off2 = 16; off2 > 0; off2 >>= 1) {
            accA += __shfl_down_sync(0xffffffffu, accA, off2);
            accB += __shfl_down_sync(0xffffffffu, accB, off2);
        }
        if (lane == 0) {
            int binb = (row / NR) * RR;
            atomicAdd(&sbins[binb], accA);
            atomicAdd(&sbins[binb + 1], accB);
        }
    }
    __syncthreads();
    if (tid < TT * RR) atomicAdd(&ssum[tid], sbins[tid]);
}

__global__ void beta_kernel(const float* __restrict__ ssum, float* __restrict__ beta) {
    int t = threadIdx.x;
    if (t < TT) {
        float s0 = ssum[t * RR + 0] * (1.0f / NN);
        float s1 = ssum[t * RR + 1] * (1.0f / NN);
        float m = fmaxf(s0, s1);
        float e0 = expf(s0 - m), e1 = expf(s1 - m);
        float inv = 1.f / (e0 + e1);
        beta[t * RR + 0] = e0 * inv;
        beta[t * RR + 1] = e1 * inv;
    }
}

// ----------------- temporal multi-head attention: warp handles 4 nodes -----------------
__global__ __launch_bounds__(256) void attn_kernel(
    const float* __restrict__ feats, const float* __restrict__ pos,
    const float* __restrict__ Wq, const float* __restrict__ Wk, const float* __restrict__ Wv,
    float* __restrict__ out) {
    extern __shared__ float sm[];
    float* sWq = sm;
    float* sWk = sm + 4096;
    float* sWv = sm + 8192;
    float* spos = sm + 12288;
    float* wb = sm + 12544;
    int tid = threadIdx.x;
    for (int i = tid; i < 4096; i += 256) {
        sWq[i] = Wq[i]; sWk[i] = Wk[i]; sWv[i] = Wv[i];
    }
    if (tid < 256) spos[tid] = pos[tid];
    __syncthreads();
    int wid = tid >> 5, lane = tid & 31;
    int nbase = blockIdx.x * 8 + wid;
    float* ti = wb + wid * 1088;
    float* q = ti + 256;
    float* k_ = q + 256;
    float* v = k_ + 256;
    float* a = v + 256;
#pragma unroll
    for (int rep = 0; rep < 4; ++rep) {
        int n = nbase + rep * (NN / 4);
#pragma unroll
        for (int m = 0; m < 8; ++m) {
            int o = m * 32 + lane;
            ti[o] = feats[(size_t)n * 256 + o] + spos[o];
        }
        __syncwarp();
        {
            const ull* wq64 = reinterpret_cast<const ull*>(sWq);
            const ull* wk64 = reinterpret_cast<const ull*>(sWk);
            const ull* wv64 = reinterpret_cast<const ull*>(sWv);
            ull q2[4] = {}, k2[4] = {}, v2[4] = {};
#pragma unroll 4
            for (int k = 0; k < 64; ++k) {
                ull wq = wq64[k * 32 + lane];
                ull wk = wk64[k * 32 + lane];
                ull wv = wv64[k * 32 + lane];
#pragma unroll
                for (int t = 0; t < 4; ++t) {
                    ull tv = pack2s(ti[t * 64 + k]);
                    q2[t] = fma2(tv, wq, q2[t]);
                    k2[t] = fma2(tv, wk, k2[t]);
                    v2[t] = fma2(tv, wv, v2[t]);
                }
            }
#pragma unroll
            for (int t = 0; t < 4; ++t) {
                reinterpret_cast<float2*>(q)[t * 32 + lane] = ull2f(q2[t]);
                reinterpret_cast<float2*>(k_)[t * 32 + lane] = ull2f(k2[t]);
                reinterpret_cast<float2*>(v)[t * 32 + lane] = ull2f(v2[t]);
            }
        }
        __syncwarp();
        if (lane < 16) {
            int h = lane >> 2, tq = lane & 3;
            float sc[4];
            for (int tk = 0; tk <= tq; ++tk) {
                float s = 0.f;
#pragma unroll
                for (int ch = 0; ch < 16; ++ch)
                    s += q[tq * 64 + h * 16 + ch] * k_[tk * 64 + h * 16 + ch];
                sc[tk] = s * 0.5f;
            }
            float mx = sc[0];
            for (int tk = 1; tk <= tq; ++tk) mx = fmaxf(mx, sc[tk]);
            float sum = 0.f;
            for (int tk = 0; tk <= tq; ++tk) { sc[tk] = __expf(sc[tk] - mx); sum += sc[tk]; }
            float inv = 1.f / sum;
            for (int tk = 0; tk < 4; ++tk)
                a[h * 16 + tq * 4 + tk] = (tk <= tq) ? sc[tk] * inv : 0.f;
        }
        __syncwarp();
        {
            int h = lane >> 3;
            const ull* v64 = reinterpret_cast<const ull*>(v);
#pragma unroll
            for (int tq = 0; tq < 4; ++tq) {
                ull acc = 0ull;
#pragma unroll
                for (int tk = 0; tk < 4; ++tk)
                    acc = fma2(pack2s(a[h * 16 + tq * 4 + tk]), v64[tk * 32 + lane], acc);
                reinterpret_cast<float2*>(out + (size_t)n * 256 + tq * 64)[lane] = ull2f(acc);
            }
        }
        __syncwarp();
    }
}

// ----------------- host launch -----------------
template <typename T>
static T* symaddr(const void* sym) {
    void* p = nullptr;
    cudaGetSymbolAddress(&p, sym);
    return (T*)p;
}

extern "C" void kernel_launch(void* const* d_in, const int* in_sizes, int n_in,
                              void* d_out, int out_size) {
    const float* x = (const float*)d_in[0];
    const int* ei = (const int*)d_in[1];
    const float* W_src = (const float*)d_in[2];
    const float* W_dst = (const float*)d_in[3];
    const float* att_src = (const float*)d_in[4];
    const float* att_dst = (const float*)d_in[5];
    const float* ra_W1 = (const float*)d_in[6];
    const float* ra_b1 = (const float*)d_in[7];
    const float* ra_W2 = (const float*)d_in[8];
    const float* Wih = (const float*)d_in[9];
    const float* Whh = (const float*)d_in[10];
    const float* bih = (const float*)d_in[11];
    const float* bhh = (const float*)d_in[12];
    const float* pos = (const float*)d_in[13];
    const float* Wq = (const float*)d_in[14];
    const float* Wk = (const float*)d_in[15];
    const float* Wv = (const float*)d_in[16];
    float* out = (float*)d_out;

    float* agg = symaddr<float>(g_agg);
    float* als = symaddr<float>(g_als);
    float* ald = symaddr<float>(g_ald);
    float* intra = symaddr<float>(g_intra);
    float* ssum = symaddr<float>(g_ssum);
    float* beta = symaddr<float>(g_beta);
    float* xg = symaddr<float>(g_xg);
    float* lh = symaddr<float>(g_lh);
    float* lc = symaddr<float>(g_lc);
    float* feats = symaddr<float>(g_feats);
    float* WihT = symaddr<float>(g_WihT);
    float* WhhT = symaddr<float>(g_WhhT);
    float* biassum = symaddr<float>(g_biassum);
    float* folds = symaddr<float>(g_folds);
    float* foldd = symaddr<float>(g_foldd);
    float* Bstack = symaddr<float>(g_Bstack);
    int* cnt = symaddr<int>(g_cnt);
    int* off = symaddr<int>(g_off);
    int* rank = symaddr<int>(g_rank);
    int* sorted = symaddr<int>(g_sorted);
    ull* wsort8 = symaddr<ull>(g_wsort8);

    const int REL_SMEM = (16384 + 256 + 256 + 8) * 4;
    const int ATT_SMEM = (12544 + 8 * 1088) * 4;
    cudaFuncSetAttribute(relation_kernel, cudaFuncAttributeMaxDynamicSharedMemorySize, REL_SMEM);
    cudaFuncSetAttribute(attn_kernel, cudaFuncAttributeMaxDynamicSharedMemorySize, ATT_SMEM);
    cudaFuncSetAttribute(gemm_intra128, cudaFuncAttributeMaxDynamicSharedMemorySize, GI_SMEM);
    cudaFuncSetAttribute(lstm_fused_kernel, cudaFuncAttributeMaxDynamicSharedMemorySize,
                         LSTMF_SMEM);

    // ---- prep (cnt zeroing fused in) + CSR/GAT front (atomic-free scatter)
    prep_kernel<<<PREP_BLOCKS, 256>>>(W_src, W_dst, att_src, att_dst, Wih, Whh, bih, bhh,
                                      folds, foldd, Bstack, WihT, WhhT, biassum, cnt);
    alshist_kernel<<<ALS_BLOCKS + HIST_BLOCKS, 256>>>(x, folds, foldd, ei, als, ald, cnt, rank);
    scan_kernel<<<ZZ, 1024>>>(cnt, off);
    scatter_kernel<<<(ZZ * EE / 2) / 256, 256>>>(ei, als, ald, off, rank, sorted, wsort8);
    gather_kernel<<<dim3(NN / 8, ZZ), 256>>>(off, sorted, wsort8, x, agg);

    // ---- batched intra GEMM (128-row tiles)
    gemm_intra128<<<dim3((NN + 127) / 128, ZZ), 256, GI_SMEM>>>(agg, Bstack, intra);

    // ---- relation aggregation (explicit ssum zero — MUST be per-call for graph replay)
    cudaMemsetAsync(ssum, 0, TT * RR * sizeof(float), 0);
    relation_kernel<<<444, 256, REL_SMEM>>>(intra, ra_W1, ra_b1, ra_W2, ssum);
    beta_kernel<<<1, 32>>>(ssum, beta);

    // ---- LSTM: beta-fused xg GEMM, then per-step fused kernels (t=0 specialized)
    gemm_xg<<<dim3(HC / 64, (TT * NN) / 64), 256>>>(intra, beta, WihT, biassum, xg);
    for (int t = 0; t < TT; ++t) {
        lstm_fused_kernel<<<(NN + 63) / 64, 256, LSTMF_SMEM>>>(xg, WhhT, lh, lc, feats, t,
                                                               t == 0 ? 1 : 0);
    }

    // ---- temporal attention (4 nodes per warp)
    attn_kernel<<<(NN + 31) / 32, 256, ATT_SMEM>>>(feats, pos, Wq, Wk, Wv, out);
}